// round 5
// baseline (speedup 1.0000x reference)
#include <cuda_runtime.h>
#include <cstdint>
#include <math.h>

#define N_TOK  4096
#define EMBED  768
#define NHEAD  12
#define DHEAD  64
#define KPATCH 256

// ---- device scratch (allocation-free: module globals) ----
__device__ float g_tok[N_TOK * EMBED];
__device__ float g_q[NHEAD * N_TOK * DHEAD];   // [h, n, d]
__device__ float g_k[NHEAD * N_TOK * DHEAD];
__device__ float g_v[NHEAD * N_TOK * DHEAD];

// ============================================================
// helpers
// ============================================================
__device__ __forceinline__ uint32_t smem_u32(const void* p) {
    uint32_t a;
    asm("{ .reg .u64 t; cvta.to.shared.u64 t, %1; cvt.u32.u64 %0, t; }"
        : "=r"(a) : "l"(p));
    return a;
}
__device__ __forceinline__ void cp16(uint32_t dst, const void* src) {
    asm volatile("cp.async.cg.shared.global [%0], [%1], 16;"
                 :: "r"(dst), "l"(src));
}
#define CP_COMMIT() asm volatile("cp.async.commit_group;" ::: "memory")
#define CP_WAIT1()  asm volatile("cp.async.wait_group 1;" ::: "memory")

__device__ __forceinline__ void mma8(float4& d, const uint32_t a[4],
                                     uint32_t b0, uint32_t b1) {
    asm volatile(
        "mma.sync.aligned.m16n8k8.row.col.f32.tf32.tf32.f32 "
        "{%0,%1,%2,%3}, {%4,%5,%6,%7}, {%8,%9}, {%0,%1,%2,%3};"
        : "+f"(d.x), "+f"(d.y), "+f"(d.z), "+f"(d.w)
        : "r"(a[0]), "r"(a[1]), "r"(a[2]), "r"(a[3]), "r"(b0), "r"(b1));
}
__device__ __forceinline__ uint32_t tf32u(float x) {
    uint32_t u;
    asm("cvt.rna.tf32.f32 %0, %1;" : "=r"(u) : "f"(x));
    return u;
}
__device__ __forceinline__ float tf32f(float x) {
    return __uint_as_float(tf32u(x));
}

// ============================================================
// Kernel 1: patch-embed GEMM (fp32, small: 1.6 GF)
// ============================================================
__global__ __launch_bounds__(256) void patch_embed_kernel(
    const float* __restrict__ x, const float* __restrict__ w,
    const float* __restrict__ bias)
{
    __shared__ float As[16][64];
    __shared__ float Bs[16][64];
    const int tid = threadIdx.x;
    const int tx = tid & 15, ty = tid >> 4;
    const int m0 = blockIdx.y * 64;
    const int n0 = blockIdx.x * 64;
    const int lm = tid >> 2;
    const int lk = (tid & 3) * 4;
    const int tok = m0 + lm;
    const int pr = tok >> 6, pc = tok & 63;

    float acc[4][4];
#pragma unroll
    for (int i = 0; i < 4; i++)
#pragma unroll
        for (int j = 0; j < 4; j++) acc[i][j] = 0.f;

    for (int kt = 0; kt < KPATCH; kt += 16) {
        const int i = (kt + lk) >> 4;
        const int j = lk;
        float4 a4 = *(const float4*)&x[(pr * 16 + i) * 1024 + pc * 16 + j];
        As[lk + 0][lm] = a4.x; As[lk + 1][lm] = a4.y;
        As[lk + 2][lm] = a4.z; As[lk + 3][lm] = a4.w;
        float4 b4 = *(const float4*)&w[(n0 + lm) * KPATCH + kt + lk];
        Bs[lk + 0][lm] = b4.x; Bs[lk + 1][lm] = b4.y;
        Bs[lk + 2][lm] = b4.z; Bs[lk + 3][lm] = b4.w;
        __syncthreads();
#pragma unroll
        for (int kk = 0; kk < 16; kk++) {
            float4 av = *(const float4*)&As[kk][ty * 4];
            float4 bv = *(const float4*)&Bs[kk][tx * 4];
            float am[4] = {av.x, av.y, av.z, av.w};
            float bn[4] = {bv.x, bv.y, bv.z, bv.w};
#pragma unroll
            for (int i2 = 0; i2 < 4; i2++)
#pragma unroll
                for (int j2 = 0; j2 < 4; j2++) acc[i2][j2] += am[i2] * bn[j2];
        }
        __syncthreads();
    }
#pragma unroll
    for (int i = 0; i < 4; i++) {
        int m = m0 + ty * 4 + i;
#pragma unroll
        for (int j = 0; j < 4; j++) {
            int n = n0 + tx * 4 + j;
            g_tok[m * EMBED + n] = acc[i][j] + bias[n];
        }
    }
}

// ============================================================
// Kernel 2: LayerNorm; outputs rounded to tf32 for downstream mma
// ============================================================
__device__ __forceinline__ float block_sum256(float v) {
    __shared__ float sh[8];
    __syncthreads();
    const int lane = threadIdx.x & 31, wrp = threadIdx.x >> 5;
#pragma unroll
    for (int o = 16; o > 0; o >>= 1) v += __shfl_xor_sync(0xffffffffu, v, o);
    if (lane == 0) sh[wrp] = v;
    __syncthreads();
    if (wrp == 0) {
        v = (lane < 8) ? sh[lane] : 0.f;
#pragma unroll
        for (int o = 4; o > 0; o >>= 1) v += __shfl_xor_sync(0xffffffffu, v, o);
        if (lane == 0) sh[0] = v;
    }
    __syncthreads();
    return sh[0];
}

__global__ __launch_bounds__(256) void ln_kernel(
    const float* __restrict__ gamma, const float* __restrict__ beta)
{
    const int n = blockIdx.x;
    const int t = threadIdx.x;
    float* row = &g_tok[n * EMBED];
    float v0 = row[t], v1 = row[t + 256], v2 = row[t + 512];
    float total = block_sum256(v0 + v1 + v2);
    float mu = total * (1.f / EMBED);
    float d0 = v0 - mu, d1 = v1 - mu, d2 = v2 - mu;
    float tot2 = block_sum256(d0 * d0 + d1 * d1 + d2 * d2);
    float inv = rsqrtf(tot2 * (1.f / EMBED) + 1e-6f);
    row[t]       = tf32f(d0 * inv * gamma[t]       + beta[t]);
    row[t + 256] = tf32f(d1 * inv * gamma[t + 256] + beta[t + 256]);
    row[t + 512] = tf32f(d2 * inv * gamma[t + 512] + beta[t + 512]);
}

// ============================================================
// Kernel 3: QKV GEMM, tf32 mma.sync (unchanged from R4)
// ============================================================
#define GP 36
#define GTILE (128 * GP)
#define QKV_SMEM (4 * GTILE * 4)

__global__ __launch_bounds__(256, 2) void qkv_kernel(const float* __restrict__ w)
{
    extern __shared__ float sm[];
    float* ab[2] = { sm,             sm + GTILE };
    float* bb[2] = { sm + 2 * GTILE, sm + 3 * GTILE };
    const uint32_t ab_u[2] = { smem_u32(ab[0]), smem_u32(ab[1]) };
    const uint32_t bb_u[2] = { smem_u32(bb[0]), smem_u32(bb[1]) };

    const int tid = threadIdx.x, wid = tid >> 5, lane = tid & 31;
    const int lj = lane & 3, lr = lane >> 2;
    const int wm = wid >> 2, wn = wid & 3;
    const int m0 = blockIdx.y * 128, n0 = blockIdx.x * 128;

    float4 acc[4][4];
#pragma unroll
    for (int i = 0; i < 4; i++)
#pragma unroll
        for (int j = 0; j < 4; j++) acc[i][j] = make_float4(0.f, 0.f, 0.f, 0.f);

#define QKV_ISSUE(KT, B) do {                                                  \
    _Pragma("unroll")                                                          \
    for (int i = 0; i < 4; i++) {                                              \
        int c = tid + i * 256;                                                 \
        int r = c >> 3, cl = c & 7;                                            \
        cp16(ab_u[B] + (r * GP + cl * 4) * 4,                                  \
             g_tok + (m0 + r) * EMBED + (KT) + cl * 4);                        \
        cp16(bb_u[B] + (r * GP + cl * 4) * 4,                                  \
             w + (n0 + r) * EMBED + (KT) + cl * 4);                            \
    } } while (0)

    QKV_ISSUE(0, 0);  CP_COMMIT();
    QKV_ISSUE(32, 1); CP_COMMIT();

    const int NIT = EMBED / 32;   // 24
    for (int it = 0; it < NIT; it++) {
        const int b = it & 1;
        CP_WAIT1();
        __syncthreads();
        const float* A = ab[b];
        const float* B = bb[b];
#pragma unroll
        for (int g = 0; g < 4; g++) {
            uint32_t af[4][4];
#pragma unroll
            for (int mt = 0; mt < 4; mt++) {
                int r0 = wm * 64 + mt * 16 + lr;
                af[mt][0] = __float_as_uint(A[r0 * GP + g * 8 + lj]);
                af[mt][1] = __float_as_uint(A[(r0 + 8) * GP + g * 8 + lj]);
                af[mt][2] = __float_as_uint(A[r0 * GP + g * 8 + lj + 4]);
                af[mt][3] = __float_as_uint(A[(r0 + 8) * GP + g * 8 + lj + 4]);
            }
#pragma unroll
            for (int nt = 0; nt < 4; nt++) {
                int c0 = wn * 32 + nt * 8 + lr;
                uint32_t b0 = __float_as_uint(B[c0 * GP + g * 8 + lj]);
                uint32_t b1 = __float_as_uint(B[c0 * GP + g * 8 + lj + 4]);
#pragma unroll
                for (int mt = 0; mt < 4; mt++) mma8(acc[mt][nt], af[mt], b0, b1);
            }
        }
        __syncthreads();
        if (it + 2 < NIT) QKV_ISSUE((it + 2) * 32, b);
        CP_COMMIT();
    }

#pragma unroll
    for (int nt = 0; nt < 4; nt++) {
        int n = n0 + wn * 32 + nt * 8 + 2 * lj;
        int s = n / EMBED;
        int r = n % EMBED;
        int hh = r / DHEAD, dd = r % DHEAD;
        float* dst = ((s == 0) ? g_q : (s == 1) ? g_k : g_v)
                   + (hh * N_TOK) * DHEAD + dd;
#pragma unroll
        for (int mt = 0; mt < 4; mt++) {
            int row = m0 + wm * 64 + mt * 16 + lr;
            float2 v0 = make_float2(tf32f(acc[mt][nt].x), tf32f(acc[mt][nt].y));
            float2 v8 = make_float2(tf32f(acc[mt][nt].z), tf32f(acc[mt][nt].w));
            *(float2*)(dst + row * DHEAD) = v0;
            *(float2*)(dst + (row + 8) * DHEAD) = v8;
        }
    }
}

// ============================================================
// Kernel 4: flash attention, tf32 mma.sync — retiled for occupancy.
// CTA = (head, 64 queries), 4 warps x 16-row strips, kv tile 64.
// 3 CTAs/SM (69.6KB smem, ~140 regs). B-frag amplification 4x (was 8x):
// crossbar/mma drops 2 -> 1 cyc, balanced with tensor pipe.
// ============================================================
#define AQ   64
#define AKV  64
#define APAD 68
#define ATILE (AKV * APAD)
#define ATT_SMEM (4 * ATILE * 4)
#define ATH  128

__global__ __launch_bounds__(ATH, 3) void attn_kernel(float* __restrict__ out)
{
    extern __shared__ float sm[];
    float* kb[2] = { sm,             sm + ATILE };
    float* vb[2] = { sm + 2 * ATILE, sm + 3 * ATILE };
    const uint32_t kb_u[2] = { smem_u32(kb[0]), smem_u32(kb[1]) };
    const uint32_t vb_u[2] = { smem_u32(vb[0]), smem_u32(vb[1]) };

    const int tid = threadIdx.x, wid = tid >> 5, lane = tid & 31;
    const int lj = lane & 3, lr = lane >> 2;
    const int h = blockIdx.y, q0 = blockIdx.x * AQ;

    const float* Kh = g_k + h * N_TOK * DHEAD;
    const float* Vh = g_v + h * N_TOK * DHEAD;

    // Q fragments (register-resident, tf32-rounded upstream)
    uint32_t qa[8][4];
    {
        const float* Q0 = g_q + (h * N_TOK + q0 + wid * 16 + lr) * DHEAD;
        const float* Q8 = Q0 + 8 * DHEAD;
#pragma unroll
        for (int g = 0; g < 8; g++) {
            qa[g][0] = __float_as_uint(Q0[8 * g + lj]);
            qa[g][1] = __float_as_uint(Q8[8 * g + lj]);
            qa[g][2] = __float_as_uint(Q0[8 * g + lj + 4]);
            qa[g][3] = __float_as_uint(Q8[8 * g + lj + 4]);
        }
    }

    float4 oacc[8];
#pragma unroll
    for (int i = 0; i < 8; i++) oacc[i] = make_float4(0.f, 0.f, 0.f, 0.f);
    float l_lo = 0.f, l_hi = 0.f;

    // K tile = 64 rows x 64 floats = 1024 16B-chunks; same for V.
    // 128 threads -> 8 K-chunks + 8 V-chunks each.
#define ATT_ISSUE(T, B) do {                                                   \
    _Pragma("unroll")                                                          \
    for (int i = 0; i < 8; i++) {                                              \
        int c = tid + i * ATH;                                                 \
        int r = c >> 4, cl = c & 15;                                           \
        cp16(kb_u[B] + (r * APAD + cl * 4) * 4,                                \
             Kh + ((T) * AKV + r) * DHEAD + cl * 4);                           \
        cp16(vb_u[B] + (r * APAD + cl * 4) * 4,                                \
             Vh + ((T) * AKV + r) * DHEAD + cl * 4);                           \
    } } while (0)

    ATT_ISSUE(0, 0); CP_COMMIT();
    ATT_ISSUE(1, 1); CP_COMMIT();

    const int NT = N_TOK / AKV;   // 64
    for (int t = 0; t < NT; t++) {
        const int b = t & 1;
        CP_WAIT1();
        __syncthreads();
        const float* K = kb[b];
        const float* V = vb[b];

        // ---- S = Q K^T : 8 n-tiles of 8 kv ----
        float4 sacc[8];
#pragma unroll
        for (int nt = 0; nt < 8; nt++) sacc[nt] = make_float4(0.f, 0.f, 0.f, 0.f);
#pragma unroll
        for (int g = 0; g < 8; g++) {
#pragma unroll
            for (int nt = 0; nt < 8; nt++) {
                const float* kp = K + (nt * 8 + lr) * APAD + g * 8 + lj;
                uint32_t b0 = __float_as_uint(kp[0]);
                uint32_t b1 = __float_as_uint(kp[4]);
                mma8(sacc[nt], qa[g], b0, b1);
            }
        }

        // ---- exp + O += P V (kv-permutation sigma(k)=2k/2k+1) ----
#pragma unroll
        for (int g = 0; g < 8; g++) {
            float p0 = __expf(sacc[g].x * 0.125f);
            float p1 = __expf(sacc[g].y * 0.125f);
            float p2 = __expf(sacc[g].z * 0.125f);
            float p3 = __expf(sacc[g].w * 0.125f);
            l_lo += p0 + p1;
            l_hi += p2 + p3;
            uint32_t pa[4] = { tf32u(p0), tf32u(p2), tf32u(p1), tf32u(p3) };
            const float* v0p = V + (8 * g + 2 * lj) * APAD + lr;
            const float* v1p = v0p + APAD;
#pragma unroll
            for (int dt = 0; dt < 8; dt++) {
                uint32_t b0 = __float_as_uint(v0p[dt * 8]);
                uint32_t b1 = __float_as_uint(v1p[dt * 8]);
                mma8(oacc[dt], pa, b0, b1);
            }
        }

        __syncthreads();
        if (t + 2 < NT) ATT_ISSUE(t + 2, b);
        CP_COMMIT();
    }

    // ---- epilogue: quad-reduce l, normalize, store ----
    l_lo += __shfl_xor_sync(0xffffffffu, l_lo, 1);
    l_lo += __shfl_xor_sync(0xffffffffu, l_lo, 2);
    l_hi += __shfl_xor_sync(0xffffffffu, l_hi, 1);
    l_hi += __shfl_xor_sync(0xffffffffu, l_hi, 2);
    const float inv_lo = 1.f / l_lo;
    const float inv_hi = 1.f / l_hi;
    const int row = q0 + wid * 16 + lr;
    float* o0 = out + row * EMBED + h * DHEAD + 2 * lj;
    float* o8 = o0 + 8 * EMBED;
#pragma unroll
    for (int dt = 0; dt < 8; dt++) {
        *(float2*)(o0 + dt * 8) = make_float2(oacc[dt].x * inv_lo,
                                              oacc[dt].y * inv_lo);
        *(float2*)(o8 + dt * 8) = make_float2(oacc[dt].z * inv_hi,
                                              oacc[dt].w * inv_hi);
    }
}

// ============================================================
extern "C" void kernel_launch(void* const* d_in, const int* in_sizes, int n_in,
                              void* d_out, int out_size)
{
    const float* x  = (const float*)d_in[0];
    const float* pw = (const float*)d_in[1];
    const float* pb = (const float*)d_in[2];
    const float* lg = (const float*)d_in[3];
    const float* lb = (const float*)d_in[4];
    const float* qw = (const float*)d_in[5];
    float* out = (float*)d_out;

    cudaFuncSetAttribute(qkv_kernel,
                         cudaFuncAttributeMaxDynamicSharedMemorySize, QKV_SMEM);
    cudaFuncSetAttribute(attn_kernel,
                         cudaFuncAttributeMaxDynamicSharedMemorySize, ATT_SMEM);

    patch_embed_kernel<<<dim3(EMBED / 64, N_TOK / 64), 256>>>(x, pw, pb);
    ln_kernel<<<N_TOK, 256>>>(lg, lb);
    qkv_kernel<<<dim3(2304 / 128, N_TOK / 128), 256, QKV_SMEM>>>(qw);
    attn_kernel<<<dim3(N_TOK / AQ, NHEAD), ATH, ATT_SMEM>>>(out);
}

// round 6
// speedup vs baseline: 1.6595x; 1.6595x over previous
#include <cuda_runtime.h>
#include <cuda_fp16.h>
#include <cstdint>
#include <math.h>

#define N_TOK  4096
#define EMBED  768
#define NHEAD  12
#define DHEAD  64
#define KPATCH 256

// ---- device scratch (allocation-free: module globals) ----
__device__ float  g_tok[N_TOK * EMBED];          // post patch-embed (fp32)
__device__ __half g_tok_h[N_TOK * EMBED];        // post-LN tokens (fp16)
__device__ __half g_wh[3 * EMBED * EMBED];       // qkv weight (fp16)
__device__ __half g_qh[NHEAD * N_TOK * DHEAD];   // [h, n, d]
__device__ __half g_kh[NHEAD * N_TOK * DHEAD];   // [h, n, d]
__device__ __half g_vt[NHEAD * DHEAD * N_TOK];   // [h, d, n]  (V transposed)

// ============================================================
// helpers
// ============================================================
__device__ __forceinline__ uint32_t smem_u32(const void* p) {
    uint32_t a;
    asm("{ .reg .u64 t; cvta.to.shared.u64 t, %1; cvt.u32.u64 %0, t; }"
        : "=r"(a) : "l"(p));
    return a;
}
__device__ __forceinline__ void cp16(uint32_t dst, const void* src) {
    asm volatile("cp.async.cg.shared.global [%0], [%1], 16;"
                 :: "r"(dst), "l"(src));
}
#define CP_COMMIT() asm volatile("cp.async.commit_group;" ::: "memory")
#define CP_WAIT1()  asm volatile("cp.async.wait_group 1;" ::: "memory")

// m16n8k16 fp16 mma, fp32 accumulate
__device__ __forceinline__ void mma16(float4& d, const uint32_t a[4],
                                      uint32_t b0, uint32_t b1) {
    asm volatile(
        "mma.sync.aligned.m16n8k16.row.col.f32.f16.f16.f32 "
        "{%0,%1,%2,%3}, {%4,%5,%6,%7}, {%8,%9}, {%0,%1,%2,%3};"
        : "+f"(d.x), "+f"(d.y), "+f"(d.z), "+f"(d.w)
        : "r"(a[0]), "r"(a[1]), "r"(a[2]), "r"(a[3]), "r"(b0), "r"(b1));
}
__device__ __forceinline__ uint32_t ldh2(const __half* p) {
    return *reinterpret_cast<const uint32_t*>(p);
}
__device__ __forceinline__ uint32_t packh2(float lo, float hi) {
    __half2 h = __floats2half2_rn(lo, hi);
    return *reinterpret_cast<uint32_t*>(&h);
}

// ============================================================
// Kernel 1: patch-embed GEMM (fp32, small: 1.6 GF)
// ============================================================
__global__ __launch_bounds__(256) void patch_embed_kernel(
    const float* __restrict__ x, const float* __restrict__ w,
    const float* __restrict__ bias)
{
    __shared__ float As[16][64];
    __shared__ float Bs[16][64];
    const int tid = threadIdx.x;
    const int tx = tid & 15, ty = tid >> 4;
    const int m0 = blockIdx.y * 64;
    const int n0 = blockIdx.x * 64;
    const int lm = tid >> 2;
    const int lk = (tid & 3) * 4;
    const int tok = m0 + lm;
    const int pr = tok >> 6, pc = tok & 63;

    float acc[4][4];
#pragma unroll
    for (int i = 0; i < 4; i++)
#pragma unroll
        for (int j = 0; j < 4; j++) acc[i][j] = 0.f;

    for (int kt = 0; kt < KPATCH; kt += 16) {
        const int i = (kt + lk) >> 4;
        const int j = lk;
        float4 a4 = *(const float4*)&x[(pr * 16 + i) * 1024 + pc * 16 + j];
        As[lk + 0][lm] = a4.x; As[lk + 1][lm] = a4.y;
        As[lk + 2][lm] = a4.z; As[lk + 3][lm] = a4.w;
        float4 b4 = *(const float4*)&w[(n0 + lm) * KPATCH + kt + lk];
        Bs[lk + 0][lm] = b4.x; Bs[lk + 1][lm] = b4.y;
        Bs[lk + 2][lm] = b4.z; Bs[lk + 3][lm] = b4.w;
        __syncthreads();
#pragma unroll
        for (int kk = 0; kk < 16; kk++) {
            float4 av = *(const float4*)&As[kk][ty * 4];
            float4 bv = *(const float4*)&Bs[kk][tx * 4];
            float am[4] = {av.x, av.y, av.z, av.w};
            float bn[4] = {bv.x, bv.y, bv.z, bv.w};
#pragma unroll
            for (int i2 = 0; i2 < 4; i2++)
#pragma unroll
                for (int j2 = 0; j2 < 4; j2++) acc[i2][j2] += am[i2] * bn[j2];
        }
        __syncthreads();
    }
#pragma unroll
    for (int i = 0; i < 4; i++) {
        int m = m0 + ty * 4 + i;
#pragma unroll
        for (int j = 0; j < 4; j++) {
            int n = n0 + tx * 4 + j;
            g_tok[m * EMBED + n] = acc[i][j] + bias[n];
        }
    }
}

// ============================================================
// Kernel 1b: qkv weight fp32 -> fp16
// ============================================================
__global__ __launch_bounds__(256) void wcvt_kernel(const float* __restrict__ w)
{
    int i = (blockIdx.x * 256 + threadIdx.x) * 4;
    float4 v = *(const float4*)(w + i);
    __half2* dst = (__half2*)(g_wh + i);
    dst[0] = __floats2half2_rn(v.x, v.y);
    dst[1] = __floats2half2_rn(v.z, v.w);
}

// ============================================================
// Kernel 2: LayerNorm -> fp16 tokens
// ============================================================
__device__ __forceinline__ float block_sum256(float v) {
    __shared__ float sh[8];
    __syncthreads();
    const int lane = threadIdx.x & 31, wrp = threadIdx.x >> 5;
#pragma unroll
    for (int o = 16; o > 0; o >>= 1) v += __shfl_xor_sync(0xffffffffu, v, o);
    if (lane == 0) sh[wrp] = v;
    __syncthreads();
    if (wrp == 0) {
        v = (lane < 8) ? sh[lane] : 0.f;
#pragma unroll
        for (int o = 4; o > 0; o >>= 1) v += __shfl_xor_sync(0xffffffffu, v, o);
        if (lane == 0) sh[0] = v;
    }
    __syncthreads();
    return sh[0];
}

__global__ __launch_bounds__(256) void ln_kernel(
    const float* __restrict__ gamma, const float* __restrict__ beta)
{
    const int n = blockIdx.x;
    const int t = threadIdx.x;
    const float* row = &g_tok[n * EMBED];
    __half* hrow = &g_tok_h[n * EMBED];
    float v0 = row[t], v1 = row[t + 256], v2 = row[t + 512];
    float total = block_sum256(v0 + v1 + v2);
    float mu = total * (1.f / EMBED);
    float d0 = v0 - mu, d1 = v1 - mu, d2 = v2 - mu;
    float tot2 = block_sum256(d0 * d0 + d1 * d1 + d2 * d2);
    float inv = rsqrtf(tot2 * (1.f / EMBED) + 1e-6f);
    hrow[t]       = __float2half(d0 * inv * gamma[t]       + beta[t]);
    hrow[t + 256] = __float2half(d1 * inv * gamma[t + 256] + beta[t + 256]);
    hrow[t + 512] = __float2half(d2 * inv * gamma[t + 512] + beta[t + 512]);
}

// ============================================================
// Kernel 3: QKV GEMM, fp16 mma m16n8k16.  C[m,n] = sum_k tok[m,k] W[n,k]
// M=4096, N=2304, K=768. CTA 128x128, k-tile 32, 8 warps (2m x 4n).
// Epilogue: Q,K -> [h,n,d] fp16;  V -> [h,d,n] fp16 (transposed).
// ============================================================
#define GPH 40                   // smem pitch in halves (80B, conflict-free)
#define GTILEH (128 * GPH)

__global__ __launch_bounds__(256, 2) void qkv_kernel()
{
    __shared__ __half hsm[4 * GTILEH];
    __half* ab[2] = { hsm,              hsm + GTILEH };
    __half* bb[2] = { hsm + 2 * GTILEH, hsm + 3 * GTILEH };
    const uint32_t ab_u[2] = { smem_u32(ab[0]), smem_u32(ab[1]) };
    const uint32_t bb_u[2] = { smem_u32(bb[0]), smem_u32(bb[1]) };

    const int tid = threadIdx.x, wid = tid >> 5, lane = tid & 31;
    const int lj = lane & 3, lr = lane >> 2;
    const int wm = wid >> 2, wn = wid & 3;
    const int m0 = blockIdx.y * 128, n0 = blockIdx.x * 128;

    float4 acc[4][4];
#pragma unroll
    for (int i = 0; i < 4; i++)
#pragma unroll
        for (int j = 0; j < 4; j++) acc[i][j] = make_float4(0.f, 0.f, 0.f, 0.f);

    // k-tile 32 halves/row: 4 chunks(16B) per row, 512 A + 512 B chunks
#define QKV_ISSUE(KT, B) do {                                                  \
    _Pragma("unroll")                                                          \
    for (int i = 0; i < 2; i++) {                                              \
        int c = tid + i * 256;                                                 \
        int r = c >> 2, cl = c & 3;                                            \
        cp16(ab_u[B] + (r * GPH + cl * 8) * 2,                                 \
             g_tok_h + (m0 + r) * EMBED + (KT) + cl * 8);                      \
        cp16(bb_u[B] + (r * GPH + cl * 8) * 2,                                 \
             g_wh + (n0 + r) * EMBED + (KT) + cl * 8);                         \
    } } while (0)

    QKV_ISSUE(0, 0);  CP_COMMIT();
    QKV_ISSUE(32, 1); CP_COMMIT();

    const int NIT = EMBED / 32;   // 24
    for (int it = 0; it < NIT; it++) {
        const int b = it & 1;
        CP_WAIT1();
        __syncthreads();
        const __half* A = ab[b];
        const __half* B = bb[b];
#pragma unroll
        for (int gc = 0; gc < 2; gc++) {
            uint32_t af[4][4];
#pragma unroll
            for (int mt = 0; mt < 4; mt++) {
                int base = (wm * 64 + mt * 16 + lr) * GPH + gc * 16 + 2 * lj;
                af[mt][0] = ldh2(A + base);
                af[mt][1] = ldh2(A + base + 8 * GPH);
                af[mt][2] = ldh2(A + base + 8);
                af[mt][3] = ldh2(A + base + 8 * GPH + 8);
            }
#pragma unroll
            for (int nt = 0; nt < 4; nt++) {
                int bbase = (wn * 32 + nt * 8 + lr) * GPH + gc * 16 + 2 * lj;
                uint32_t b0 = ldh2(B + bbase);
                uint32_t b1 = ldh2(B + bbase + 8);
#pragma unroll
                for (int mt = 0; mt < 4; mt++) mma16(acc[mt][nt], af[mt], b0, b1);
            }
        }
        __syncthreads();
        if (it + 2 < NIT) QKV_ISSUE((it + 2) * 32, b);
        CP_COMMIT();
    }

    // epilogue: n pair (2lj, 2lj+1) contiguous
#pragma unroll
    for (int nt = 0; nt < 4; nt++) {
        int n = n0 + wn * 32 + nt * 8 + 2 * lj;
        int s = n / EMBED;
        int r = n % EMBED;
        int hh = r / DHEAD, dd = r % DHEAD;
#pragma unroll
        for (int mt = 0; mt < 4; mt++) {
            int row = m0 + wm * 64 + mt * 16 + lr;
            if (s < 2) {
                __half* dst = ((s == 0) ? g_qh : g_kh)
                            + (hh * N_TOK + row) * DHEAD + dd;
                *(__half2*)dst = __floats2half2_rn(acc[mt][nt].x, acc[mt][nt].y);
                *(__half2*)(dst + 8 * DHEAD) =
                    __floats2half2_rn(acc[mt][nt].z, acc[mt][nt].w);
            } else {
                __half* dst = g_vt + (hh * DHEAD + dd) * N_TOK + row;
                dst[0]          = __float2half(acc[mt][nt].x);
                dst[N_TOK]      = __float2half(acc[mt][nt].y);
                dst[8]          = __float2half(acc[mt][nt].z);
                dst[N_TOK + 8]  = __float2half(acc[mt][nt].w);
            }
        }
    }
}

// ============================================================
// Kernel 4: flash attention, fp16 mma m16n8k16.
// CTA = (head, 64 queries), 4 warps x 16-row strips, kv tile 64.
// K smem [64 kv][72 halves pitch]; V^T smem [64 d][72 pitch].
// Exp'd S accumulators pack directly into PV A-frags (no permutation).
// ============================================================
#define AQ   64
#define AKV  64
#define KPITCH 72
#define ATILEH (AKV * KPITCH)
#define ATH  128

__global__ __launch_bounds__(ATH, 3) void attn_kernel(float* __restrict__ out)
{
    __shared__ __half hsm[4 * ATILEH];
    __half* kb[2] = { hsm,              hsm + ATILEH };
    __half* vb[2] = { hsm + 2 * ATILEH, hsm + 3 * ATILEH };
    const uint32_t kb_u[2] = { smem_u32(kb[0]), smem_u32(kb[1]) };
    const uint32_t vb_u[2] = { smem_u32(vb[0]), smem_u32(vb[1]) };

    const int tid = threadIdx.x, wid = tid >> 5, lane = tid & 31;
    const int lj = lane & 3, lr = lane >> 2;
    const int h = blockIdx.y, q0 = blockIdx.x * AQ;

    const __half* Kh  = g_kh + h * N_TOK * DHEAD;
    const __half* Vth = g_vt + h * DHEAD * N_TOK;

    // Q fragments (fp16, register-resident)
    uint32_t qa[4][4];
    {
        const __half* Q0 = g_qh + (h * N_TOK + q0 + wid * 16 + lr) * DHEAD;
#pragma unroll
        for (int gc = 0; gc < 4; gc++) {
            int base = gc * 16 + 2 * lj;
            qa[gc][0] = ldh2(Q0 + base);
            qa[gc][1] = ldh2(Q0 + 8 * DHEAD + base);
            qa[gc][2] = ldh2(Q0 + base + 8);
            qa[gc][3] = ldh2(Q0 + 8 * DHEAD + base + 8);
        }
    }

    float4 oacc[8];
#pragma unroll
    for (int i = 0; i < 8; i++) oacc[i] = make_float4(0.f, 0.f, 0.f, 0.f);
    float l_lo = 0.f, l_hi = 0.f;

    // K tile: 64 rows x 64 halves = 8 chunks/row -> 512; V^T same.
#define ATT_ISSUE(T, B) do {                                                   \
    _Pragma("unroll")                                                          \
    for (int i = 0; i < 4; i++) {                                              \
        int c = tid + i * ATH;                                                 \
        int r = c >> 3, cl = c & 7;                                            \
        cp16(kb_u[B] + (r * KPITCH + cl * 8) * 2,                              \
             Kh + ((T) * AKV + r) * DHEAD + cl * 8);                           \
        cp16(vb_u[B] + (r * KPITCH + cl * 8) * 2,                              \
             Vth + r * N_TOK + (T) * AKV + cl * 8);                            \
    } } while (0)

    ATT_ISSUE(0, 0); CP_COMMIT();
    ATT_ISSUE(1, 1); CP_COMMIT();

    const int NT = N_TOK / AKV;   // 64
    for (int t = 0; t < NT; t++) {
        const int b = t & 1;
        CP_WAIT1();
        __syncthreads();
        const __half* K = kb[b];
        const __half* V = vb[b];

        // ---- S = Q K^T : 8 n-tiles, 4 k16 chunks ----
        float4 sacc[8];
#pragma unroll
        for (int nt = 0; nt < 8; nt++) sacc[nt] = make_float4(0.f, 0.f, 0.f, 0.f);
#pragma unroll
        for (int gc = 0; gc < 4; gc++) {
#pragma unroll
            for (int nt = 0; nt < 8; nt++) {
                const __half* kp = K + (nt * 8 + lr) * KPITCH + gc * 16 + 2 * lj;
                uint32_t b0 = ldh2(kp);
                uint32_t b1 = ldh2(kp + 8);
                mma16(sacc[nt], qa[gc], b0, b1);
            }
        }

        // ---- exp + O += P V (S c-frags map directly to A-frags) ----
#pragma unroll
        for (int c = 0; c < 4; c++) {
            float4 s0 = sacc[2 * c], s1 = sacc[2 * c + 1];
            float p0 = __expf(s0.x * 0.125f);
            float p1 = __expf(s0.y * 0.125f);
            float p2 = __expf(s0.z * 0.125f);
            float p3 = __expf(s0.w * 0.125f);
            float p4 = __expf(s1.x * 0.125f);
            float p5 = __expf(s1.y * 0.125f);
            float p6 = __expf(s1.z * 0.125f);
            float p7 = __expf(s1.w * 0.125f);
            l_lo += p0 + p1 + p4 + p5;
            l_hi += p2 + p3 + p6 + p7;
            uint32_t pa[4] = { packh2(p0, p1), packh2(p2, p3),
                               packh2(p4, p5), packh2(p6, p7) };
#pragma unroll
            for (int dt = 0; dt < 8; dt++) {
                const __half* vp = V + (dt * 8 + lr) * KPITCH + c * 16 + 2 * lj;
                uint32_t b0 = ldh2(vp);
                uint32_t b1 = ldh2(vp + 8);
                mma16(oacc[dt], pa, b0, b1);
            }
        }

        __syncthreads();
        if (t + 2 < NT) ATT_ISSUE(t + 2, b);
        CP_COMMIT();
    }

    // ---- epilogue: quad-reduce l, normalize, store ----
    l_lo += __shfl_xor_sync(0xffffffffu, l_lo, 1);
    l_lo += __shfl_xor_sync(0xffffffffu, l_lo, 2);
    l_hi += __shfl_xor_sync(0xffffffffu, l_hi, 1);
    l_hi += __shfl_xor_sync(0xffffffffu, l_hi, 2);
    const float inv_lo = 1.f / l_lo;
    const float inv_hi = 1.f / l_hi;
    const int row = q0 + wid * 16 + lr;
    float* o0 = out + row * EMBED + h * DHEAD + 2 * lj;
    float* o8 = o0 + 8 * EMBED;
#pragma unroll
    for (int dt = 0; dt < 8; dt++) {
        *(float2*)(o0 + dt * 8) = make_float2(oacc[dt].x * inv_lo,
                                              oacc[dt].y * inv_lo);
        *(float2*)(o8 + dt * 8) = make_float2(oacc[dt].z * inv_hi,
                                              oacc[dt].w * inv_hi);
    }
}

// ============================================================
extern "C" void kernel_launch(void* const* d_in, const int* in_sizes, int n_in,
                              void* d_out, int out_size)
{
    const float* x  = (const float*)d_in[0];
    const float* pw = (const float*)d_in[1];
    const float* pb = (const float*)d_in[2];
    const float* lg = (const float*)d_in[3];
    const float* lb = (const float*)d_in[4];
    const float* qw = (const float*)d_in[5];
    float* out = (float*)d_out;

    patch_embed_kernel<<<dim3(EMBED / 64, N_TOK / 64), 256>>>(x, pw, pb);
    wcvt_kernel<<<(3 * EMBED * EMBED) / 1024, 256>>>(qw);
    ln_kernel<<<N_TOK, 256>>>(lg, lb);
    qkv_kernel<<<dim3(2304 / 128, N_TOK / 128), 256>>>();
    attn_kernel<<<dim3(N_TOK / AQ, NHEAD), ATH>>>(out);
}

// round 7
// speedup vs baseline: 2.1281x; 1.2824x over previous
#include <cuda_runtime.h>
#include <cuda_fp16.h>
#include <cstdint>
#include <math.h>

#define N_TOK  4096
#define EMBED  768
#define NHEAD  12
#define DHEAD  64
#define KPATCH 256

// ---- device scratch (allocation-free: module globals) ----
__device__ float  g_tok[N_TOK * EMBED];          // post patch-embed (fp32)
__device__ __half g_tok_h[N_TOK * EMBED];        // post-LN tokens (fp16)
__device__ __half g_wh[3 * EMBED * EMBED];       // qkv weight (fp16)
__device__ __half g_qh[NHEAD * N_TOK * DHEAD];   // [h, n, d]
__device__ __half g_kh[NHEAD * N_TOK * DHEAD];   // [h, n, d]
__device__ __half g_vt[NHEAD * DHEAD * N_TOK];   // [h, d, n]  (V transposed)

// ============================================================
// helpers
// ============================================================
__device__ __forceinline__ uint32_t smem_u32(const void* p) {
    uint32_t a;
    asm("{ .reg .u64 t; cvta.to.shared.u64 t, %1; cvt.u32.u64 %0, t; }"
        : "=r"(a) : "l"(p));
    return a;
}
__device__ __forceinline__ void cp16(uint32_t dst, const void* src) {
    asm volatile("cp.async.cg.shared.global [%0], [%1], 16;"
                 :: "r"(dst), "l"(src));
}
#define CP_COMMIT() asm volatile("cp.async.commit_group;" ::: "memory")
#define CP_WAIT1()  asm volatile("cp.async.wait_group 1;" ::: "memory")

// m16n8k16 fp16 mma, fp32 accumulate
__device__ __forceinline__ void mma16(float4& d, const uint32_t a[4],
                                      uint32_t b0, uint32_t b1) {
    asm volatile(
        "mma.sync.aligned.m16n8k16.row.col.f32.f16.f16.f32 "
        "{%0,%1,%2,%3}, {%4,%5,%6,%7}, {%8,%9}, {%0,%1,%2,%3};"
        : "+f"(d.x), "+f"(d.y), "+f"(d.z), "+f"(d.w)
        : "r"(a[0]), "r"(a[1]), "r"(a[2]), "r"(a[3]), "r"(b0), "r"(b1));
}
#define LDSM_X4(r0, r1, r2, r3, addr) \
    asm volatile("ldmatrix.sync.aligned.m8n8.x4.shared.b16 {%0,%1,%2,%3}, [%4];" \
        : "=r"(r0), "=r"(r1), "=r"(r2), "=r"(r3) : "r"(addr))

__device__ __forceinline__ uint32_t ldh2(const __half* p) {
    return *reinterpret_cast<const uint32_t*>(p);
}
__device__ __forceinline__ uint32_t packh2(float lo, float hi) {
    __half2 h = __floats2half2_rn(lo, hi);
    return *reinterpret_cast<uint32_t*>(&h);
}

// ============================================================
// Kernel 1: patch-embed GEMM (fp32, small: 1.6 GF)
// ============================================================
__global__ __launch_bounds__(256) void patch_embed_kernel(
    const float* __restrict__ x, const float* __restrict__ w,
    const float* __restrict__ bias)
{
    __shared__ float As[16][64];
    __shared__ float Bs[16][64];
    const int tid = threadIdx.x;
    const int tx = tid & 15, ty = tid >> 4;
    const int m0 = blockIdx.y * 64;
    const int n0 = blockIdx.x * 64;
    const int lm = tid >> 2;
    const int lk = (tid & 3) * 4;
    const int tok = m0 + lm;
    const int pr = tok >> 6, pc = tok & 63;

    float acc[4][4];
#pragma unroll
    for (int i = 0; i < 4; i++)
#pragma unroll
        for (int j = 0; j < 4; j++) acc[i][j] = 0.f;

    for (int kt = 0; kt < KPATCH; kt += 16) {
        const int i = (kt + lk) >> 4;
        const int j = lk;
        float4 a4 = *(const float4*)&x[(pr * 16 + i) * 1024 + pc * 16 + j];
        As[lk + 0][lm] = a4.x; As[lk + 1][lm] = a4.y;
        As[lk + 2][lm] = a4.z; As[lk + 3][lm] = a4.w;
        float4 b4 = *(const float4*)&w[(n0 + lm) * KPATCH + kt + lk];
        Bs[lk + 0][lm] = b4.x; Bs[lk + 1][lm] = b4.y;
        Bs[lk + 2][lm] = b4.z; Bs[lk + 3][lm] = b4.w;
        __syncthreads();
#pragma unroll
        for (int kk = 0; kk < 16; kk++) {
            float4 av = *(const float4*)&As[kk][ty * 4];
            float4 bv = *(const float4*)&Bs[kk][tx * 4];
            float am[4] = {av.x, av.y, av.z, av.w};
            float bn[4] = {bv.x, bv.y, bv.z, bv.w};
#pragma unroll
            for (int i2 = 0; i2 < 4; i2++)
#pragma unroll
                for (int j2 = 0; j2 < 4; j2++) acc[i2][j2] += am[i2] * bn[j2];
        }
        __syncthreads();
    }
#pragma unroll
    for (int i = 0; i < 4; i++) {
        int m = m0 + ty * 4 + i;
#pragma unroll
        for (int j = 0; j < 4; j++) {
            int n = n0 + tx * 4 + j;
            g_tok[m * EMBED + n] = acc[i][j] + bias[n];
        }
    }
}

// ============================================================
// Kernel 1b: qkv weight fp32 -> fp16
// ============================================================
__global__ __launch_bounds__(256) void wcvt_kernel(const float* __restrict__ w)
{
    int i = (blockIdx.x * 256 + threadIdx.x) * 4;
    float4 v = *(const float4*)(w + i);
    __half2* dst = (__half2*)(g_wh + i);
    dst[0] = __floats2half2_rn(v.x, v.y);
    dst[1] = __floats2half2_rn(v.z, v.w);
}

// ============================================================
// Kernel 2: LayerNorm -> fp16 tokens
// ============================================================
__device__ __forceinline__ float block_sum256(float v) {
    __shared__ float sh[8];
    __syncthreads();
    const int lane = threadIdx.x & 31, wrp = threadIdx.x >> 5;
#pragma unroll
    for (int o = 16; o > 0; o >>= 1) v += __shfl_xor_sync(0xffffffffu, v, o);
    if (lane == 0) sh[wrp] = v;
    __syncthreads();
    if (wrp == 0) {
        v = (lane < 8) ? sh[lane] : 0.f;
#pragma unroll
        for (int o = 4; o > 0; o >>= 1) v += __shfl_xor_sync(0xffffffffu, v, o);
        if (lane == 0) sh[0] = v;
    }
    __syncthreads();
    return sh[0];
}

__global__ __launch_bounds__(256) void ln_kernel(
    const float* __restrict__ gamma, const float* __restrict__ beta)
{
    const int n = blockIdx.x;
    const int t = threadIdx.x;
    const float* row = &g_tok[n * EMBED];
    __half* hrow = &g_tok_h[n * EMBED];
    float v0 = row[t], v1 = row[t + 256], v2 = row[t + 512];
    float total = block_sum256(v0 + v1 + v2);
    float mu = total * (1.f / EMBED);
    float d0 = v0 - mu, d1 = v1 - mu, d2 = v2 - mu;
    float tot2 = block_sum256(d0 * d0 + d1 * d1 + d2 * d2);
    float inv = rsqrtf(tot2 * (1.f / EMBED) + 1e-6f);
    hrow[t]       = __float2half(d0 * inv * gamma[t]       + beta[t]);
    hrow[t + 256] = __float2half(d1 * inv * gamma[t + 256] + beta[t + 256]);
    hrow[t + 512] = __float2half(d2 * inv * gamma[t + 512] + beta[t + 512]);
}

// ============================================================
// Kernel 3: QKV GEMM, fp16 mma + ldmatrix, k-tile 64.
// CTA 128x128, 8 warps (2m x 4n), double-buffered dynamic smem.
// ============================================================
#define GPH2 72                       // smem pitch in halves (144B)
#define GT2  (128 * GPH2)
#define QKV_SMEM (4 * GT2 * 2)        // 73728 B

__global__ __launch_bounds__(256, 2) void qkv_kernel()
{
    extern __shared__ __half hsm[];
    __half* ab[2] = { hsm,           hsm + GT2 };
    __half* bb[2] = { hsm + 2 * GT2, hsm + 3 * GT2 };
    const uint32_t ab_u[2] = { smem_u32(ab[0]), smem_u32(ab[1]) };
    const uint32_t bb_u[2] = { smem_u32(bb[0]), smem_u32(bb[1]) };

    const int tid = threadIdx.x, wid = tid >> 5, lane = tid & 31;
    const int lj = lane & 3, lr = lane >> 2;
    const int wm = wid >> 2, wn = wid & 3;
    const int m0 = blockIdx.y * 128, n0 = blockIdx.x * 128;

    // ldmatrix lane geometry
    const int aRow = ((lane >> 3) & 1) * 8 + (lane & 7);  // + col (lane>>4)*8
    const int aCol = (lane >> 4) * 8;
    const int bRow = (lane >> 4) * 8 + (lane & 7);        // + col ((lane>>3)&1)*8
    const int bCol = ((lane >> 3) & 1) * 8;

    float4 acc[4][4];
#pragma unroll
    for (int i = 0; i < 4; i++)
#pragma unroll
        for (int j = 0; j < 4; j++) acc[i][j] = make_float4(0.f, 0.f, 0.f, 0.f);

    // k-tile 64 halves/row: 8 chunks(16B)/row -> 1024 chunks per matrix
#define QKV_ISSUE(KT, B) do {                                                  \
    _Pragma("unroll")                                                          \
    for (int i = 0; i < 4; i++) {                                              \
        int c = tid + i * 256;                                                 \
        int r = c >> 3, cl = c & 7;                                            \
        cp16(ab_u[B] + (r * GPH2 + cl * 8) * 2,                                \
             g_tok_h + (m0 + r) * EMBED + (KT) + cl * 8);                      \
        cp16(bb_u[B] + (r * GPH2 + cl * 8) * 2,                                \
             g_wh + (n0 + r) * EMBED + (KT) + cl * 8);                         \
    } } while (0)

    QKV_ISSUE(0, 0);  CP_COMMIT();
    QKV_ISSUE(64, 1); CP_COMMIT();

    const int NIT = EMBED / 64;   // 12
    for (int it = 0; it < NIT; it++) {
        const int b = it & 1;
        CP_WAIT1();
        __syncthreads();
        const uint32_t Au = ab_u[b];
        const uint32_t Bu = bb_u[b];
#pragma unroll
        for (int gc = 0; gc < 4; gc++) {
            uint32_t af[4][4];
#pragma unroll
            for (int mt = 0; mt < 4; mt++) {
                uint32_t addr = Au + (((wm * 64 + mt * 16 + aRow) * GPH2)
                                      + gc * 16 + aCol) * 2;
                LDSM_X4(af[mt][0], af[mt][1], af[mt][2], af[mt][3], addr);
            }
#pragma unroll
            for (int j = 0; j < 2; j++) {
                uint32_t b0, b1, b2, b3;
                uint32_t addr = Bu + (((wn * 32 + j * 16 + bRow) * GPH2)
                                      + gc * 16 + bCol) * 2;
                LDSM_X4(b0, b1, b2, b3, addr);
#pragma unroll
                for (int mt = 0; mt < 4; mt++) {
                    mma16(acc[mt][2 * j],     af[mt], b0, b1);
                    mma16(acc[mt][2 * j + 1], af[mt], b2, b3);
                }
            }
        }
        __syncthreads();
        if (it + 2 < NIT) QKV_ISSUE((it + 2) * 64, b);
        CP_COMMIT();
    }

    // epilogue: n pair (2lj, 2lj+1) contiguous
#pragma unroll
    for (int nt = 0; nt < 4; nt++) {
        int n = n0 + wn * 32 + nt * 8 + 2 * lj;
        int s = n / EMBED;
        int r = n % EMBED;
        int hh = r / DHEAD, dd = r % DHEAD;
#pragma unroll
        for (int mt = 0; mt < 4; mt++) {
            int row = m0 + wm * 64 + mt * 16 + lr;
            if (s < 2) {
                __half* dst = ((s == 0) ? g_qh : g_kh)
                            + (hh * N_TOK + row) * DHEAD + dd;
                *(__half2*)dst = __floats2half2_rn(acc[mt][nt].x, acc[mt][nt].y);
                *(__half2*)(dst + 8 * DHEAD) =
                    __floats2half2_rn(acc[mt][nt].z, acc[mt][nt].w);
            } else {
                __half* dst = g_vt + (hh * DHEAD + dd) * N_TOK + row;
                dst[0]          = __float2half(acc[mt][nt].x);
                dst[N_TOK]      = __float2half(acc[mt][nt].y);
                dst[8]          = __float2half(acc[mt][nt].z);
                dst[N_TOK + 8]  = __float2half(acc[mt][nt].w);
            }
        }
    }
}

// ============================================================
// Kernel 4: flash attention, fp16 mma + ldmatrix, fused S/exp/PV per
// 16-kv chunk, l via ones-column mma (B-frag = const 1.0h).
// CTA = (head, 64 q), 4 warps, kv tile 64, 4 CTAs/SM.
// ============================================================
#define AQ   64
#define AKV  64
#define KPITCH 72
#define ATILEH (AKV * KPITCH)
#define ATH  128

__global__ __launch_bounds__(ATH, 4) void attn_kernel(float* __restrict__ out)
{
    __shared__ __half hsm[4 * ATILEH];           // 36,864 B
    __half* kb[2] = { hsm,              hsm + ATILEH };
    __half* vb[2] = { hsm + 2 * ATILEH, hsm + 3 * ATILEH };
    const uint32_t kb_u[2] = { smem_u32(kb[0]), smem_u32(kb[1]) };
    const uint32_t vb_u[2] = { smem_u32(vb[0]), smem_u32(vb[1]) };

    const int tid = threadIdx.x, wid = tid >> 5, lane = tid & 31;
    const int lj = lane & 3, lr = lane >> 2;
    const int h = blockIdx.y, q0 = blockIdx.x * AQ;

    const int bRow = (lane >> 4) * 8 + (lane & 7);
    const int bCol = ((lane >> 3) & 1) * 8;
    const uint32_t ONEH2 = 0x3C003C00u;

    const __half* Kh  = g_kh + h * N_TOK * DHEAD;
    const __half* Vth = g_vt + h * DHEAD * N_TOK;

    // Q fragments (fp16, register-resident)
    uint32_t qa[4][4];
    {
        const __half* Q0 = g_qh + (h * N_TOK + q0 + wid * 16 + lr) * DHEAD;
#pragma unroll
        for (int gc = 0; gc < 4; gc++) {
            int base = gc * 16 + 2 * lj;
            qa[gc][0] = ldh2(Q0 + base);
            qa[gc][1] = ldh2(Q0 + 8 * DHEAD + base);
            qa[gc][2] = ldh2(Q0 + base + 8);
            qa[gc][3] = ldh2(Q0 + 8 * DHEAD + base + 8);
        }
    }

    float4 oacc[8];
#pragma unroll
    for (int i = 0; i < 8; i++) oacc[i] = make_float4(0.f, 0.f, 0.f, 0.f);
    float4 lacc = make_float4(0.f, 0.f, 0.f, 0.f);

    // K tile: 64 rows x 64 halves = 8 chunks/row -> 512; V^T same.
#define ATT_ISSUE(T, B) do {                                                   \
    _Pragma("unroll")                                                          \
    for (int i = 0; i < 4; i++) {                                              \
        int c = tid + i * ATH;                                                 \
        int r = c >> 3, cl = c & 7;                                            \
        cp16(kb_u[B] + (r * KPITCH + cl * 8) * 2,                              \
             Kh + ((T) * AKV + r) * DHEAD + cl * 8);                           \
        cp16(vb_u[B] + (r * KPITCH + cl * 8) * 2,                              \
             Vth + r * N_TOK + (T) * AKV + cl * 8);                            \
    } } while (0)

    ATT_ISSUE(0, 0); CP_COMMIT();
    ATT_ISSUE(1, 1); CP_COMMIT();

    const int NT = N_TOK / AKV;   // 64
    for (int t = 0; t < NT; t++) {
        const int b = t & 1;
        CP_WAIT1();
        __syncthreads();
        const uint32_t Ku = kb_u[b];
        const uint32_t Vu = vb_u[b];

#pragma unroll
        for (int pair = 0; pair < 4; pair++) {    // 16-kv chunk
            float4 s0 = make_float4(0.f, 0.f, 0.f, 0.f);
            float4 s1 = make_float4(0.f, 0.f, 0.f, 0.f);
#pragma unroll
            for (int gc = 0; gc < 4; gc++) {
                uint32_t k0, k1, k2, k3;
                uint32_t addr = Ku + (((pair * 16 + bRow) * KPITCH)
                                      + gc * 16 + bCol) * 2;
                LDSM_X4(k0, k1, k2, k3, addr);
                mma16(s0, qa[gc], k0, k1);
                mma16(s1, qa[gc], k2, k3);
            }
            float p0 = __expf(s0.x * 0.125f);
            float p1 = __expf(s0.y * 0.125f);
            float p2 = __expf(s0.z * 0.125f);
            float p3 = __expf(s0.w * 0.125f);
            float p4 = __expf(s1.x * 0.125f);
            float p5 = __expf(s1.y * 0.125f);
            float p6 = __expf(s1.z * 0.125f);
            float p7 = __expf(s1.w * 0.125f);
            uint32_t pa[4] = { packh2(p0, p1), packh2(p2, p3),
                               packh2(p4, p5), packh2(p6, p7) };
#pragma unroll
            for (int dtj = 0; dtj < 4; dtj++) {
                uint32_t v0, v1, v2, v3;
                uint32_t addr = Vu + (((dtj * 16 + bRow) * KPITCH)
                                      + pair * 16 + bCol) * 2;
                LDSM_X4(v0, v1, v2, v3, addr);
                mma16(oacc[2 * dtj],     pa, v0, v1);
                mma16(oacc[2 * dtj + 1], pa, v2, v3);
            }
            mma16(lacc, pa, ONEH2, ONEH2);        // l = row-sum of P
        }

        __syncthreads();
        if (t + 2 < NT) ATT_ISSUE(t + 2, b);
        CP_COMMIT();
    }

    // ---- epilogue: l comes straight out of lacc (no shuffles) ----
    const float inv_lo = 1.f / lacc.x;
    const float inv_hi = 1.f / lacc.z;
    const int row = q0 + wid * 16 + lr;
    float* o0 = out + row * EMBED + h * DHEAD + 2 * lj;
    float* o8 = o0 + 8 * EMBED;
#pragma unroll
    for (int dt = 0; dt < 8; dt++) {
        *(float2*)(o0 + dt * 8) = make_float2(oacc[dt].x * inv_lo,
                                              oacc[dt].y * inv_lo);
        *(float2*)(o8 + dt * 8) = make_float2(oacc[dt].z * inv_hi,
                                              oacc[dt].w * inv_hi);
    }
}

// ============================================================
extern "C" void kernel_launch(void* const* d_in, const int* in_sizes, int n_in,
                              void* d_out, int out_size)
{
    const float* x  = (const float*)d_in[0];
    const float* pw = (const float*)d_in[1];
    const float* pb = (const float*)d_in[2];
    const float* lg = (const float*)d_in[3];
    const float* lb = (const float*)d_in[4];
    const float* qw = (const float*)d_in[5];
    float* out = (float*)d_out;

    cudaFuncSetAttribute(qkv_kernel,
                         cudaFuncAttributeMaxDynamicSharedMemorySize, QKV_SMEM);

    patch_embed_kernel<<<dim3(EMBED / 64, N_TOK / 64), 256>>>(x, pw, pb);
    wcvt_kernel<<<(3 * EMBED * EMBED) / 1024, 256>>>(qw);
    ln_kernel<<<N_TOK, 256>>>(lg, lb);
    qkv_kernel<<<dim3(2304 / 128, N_TOK / 128), 256, QKV_SMEM>>>();
    attn_kernel<<<dim3(N_TOK / AQ, NHEAD), ATH>>>(out);
}

// round 8
// speedup vs baseline: 2.6085x; 1.2257x over previous
#include <cuda_runtime.h>
#include <cuda_fp16.h>
#include <cstdint>
#include <math.h>

#define N_TOK  4096
#define EMBED  768
#define NHEAD  12
#define DHEAD  64
#define KPATCH 256

// ---- device scratch (allocation-free: module globals) ----
__device__ float  g_tok[N_TOK * EMBED];          // post patch-embed (fp32)
__device__ __half g_tok_h[N_TOK * EMBED];        // post-LN tokens (fp16)
__device__ __half g_xh[1024 * 1024];             // image (fp16)
__device__ __half g_wph[EMBED * KPATCH];         // patch weight (fp16)
__device__ __half g_wh[3 * EMBED * EMBED];       // qkv weight (fp16)
__device__ __half g_qh[NHEAD * N_TOK * DHEAD];   // [h, n, d]
__device__ __half g_kh[NHEAD * N_TOK * DHEAD];   // [h, n, d]
__device__ __half g_vt[NHEAD * DHEAD * N_TOK];   // [h, d, n]  (V transposed)

// ============================================================
// helpers
// ============================================================
__device__ __forceinline__ uint32_t smem_u32(const void* p) {
    uint32_t a;
    asm("{ .reg .u64 t; cvta.to.shared.u64 t, %1; cvt.u32.u64 %0, t; }"
        : "=r"(a) : "l"(p));
    return a;
}
__device__ __forceinline__ void cp16(uint32_t dst, const void* src) {
    asm volatile("cp.async.cg.shared.global [%0], [%1], 16;"
                 :: "r"(dst), "l"(src));
}
#define CP_COMMIT() asm volatile("cp.async.commit_group;" ::: "memory")
#define CP_WAIT1()  asm volatile("cp.async.wait_group 1;" ::: "memory")

// m16n8k16 fp16 mma, fp32 accumulate
__device__ __forceinline__ void mma16(float4& d, const uint32_t a[4],
                                      uint32_t b0, uint32_t b1) {
    asm volatile(
        "mma.sync.aligned.m16n8k16.row.col.f32.f16.f16.f32 "
        "{%0,%1,%2,%3}, {%4,%5,%6,%7}, {%8,%9}, {%0,%1,%2,%3};"
        : "+f"(d.x), "+f"(d.y), "+f"(d.z), "+f"(d.w)
        : "r"(a[0]), "r"(a[1]), "r"(a[2]), "r"(a[3]), "r"(b0), "r"(b1));
}
#define LDSM_X4(r0, r1, r2, r3, addr) \
    asm volatile("ldmatrix.sync.aligned.m8n8.x4.shared.b16 {%0,%1,%2,%3}, [%4];" \
        : "=r"(r0), "=r"(r1), "=r"(r2), "=r"(r3) : "r"(addr))

__device__ __forceinline__ uint32_t ldh2(const __half* p) {
    return *reinterpret_cast<const uint32_t*>(p);
}
__device__ __forceinline__ uint32_t packh2(float lo, float hi) {
    __half2 h = __floats2half2_rn(lo, hi);
    return *reinterpret_cast<uint32_t*>(&h);
}

// ============================================================
// converters: image / patch-weight / qkv-weight  fp32 -> fp16
// ============================================================
__global__ __launch_bounds__(256) void xcvt_kernel(const float* __restrict__ x)
{
    int i = (blockIdx.x * 256 + threadIdx.x) * 4;
    float4 v = *(const float4*)(x + i);
    __half2* dst = (__half2*)(g_xh + i);
    dst[0] = __floats2half2_rn(v.x, v.y);
    dst[1] = __floats2half2_rn(v.z, v.w);
}
__global__ __launch_bounds__(256) void wpcvt_kernel(const float* __restrict__ w)
{
    int i = (blockIdx.x * 256 + threadIdx.x) * 4;
    float4 v = *(const float4*)(w + i);
    __half2* dst = (__half2*)(g_wph + i);
    dst[0] = __floats2half2_rn(v.x, v.y);
    dst[1] = __floats2half2_rn(v.z, v.w);
}
__global__ __launch_bounds__(256) void wcvt_kernel(const float* __restrict__ w)
{
    int i = (blockIdx.x * 256 + threadIdx.x) * 4;
    float4 v = *(const float4*)(w + i);
    __half2* dst = (__half2*)(g_wh + i);
    dst[0] = __floats2half2_rn(v.x, v.y);
    dst[1] = __floats2half2_rn(v.z, v.w);
}

// ============================================================
// smem geometry shared by GEMM kernels
// ============================================================
#define GPH2 72                       // smem pitch in halves (144B)
#define GT2  (128 * GPH2)
#define GEMM_SMEM (4 * GT2 * 2)       // 73728 B

// ============================================================
// Kernel 1: patch-embed GEMM, fp16 mma.  tok[m,n] = patch[m,:]·Wp[n,:] + b[n]
// M=4096, N=768, K=256. CTA 128x128, k-tile 64, writes fp32 g_tok.
// ============================================================
__global__ __launch_bounds__(256, 2) void patch_mma_kernel(
    const float* __restrict__ bias)
{
    extern __shared__ __half hsm[];
    __half* ab[2] = { hsm,           hsm + GT2 };
    __half* bb[2] = { hsm + 2 * GT2, hsm + 3 * GT2 };
    const uint32_t ab_u[2] = { smem_u32(ab[0]), smem_u32(ab[1]) };
    const uint32_t bb_u[2] = { smem_u32(bb[0]), smem_u32(bb[1]) };

    const int tid = threadIdx.x, wid = tid >> 5, lane = tid & 31;
    const int lj = lane & 3, lr = lane >> 2;
    const int wm = wid >> 2, wn = wid & 3;
    const int m0 = blockIdx.y * 128, n0 = blockIdx.x * 128;

    const int aRow = ((lane >> 3) & 1) * 8 + (lane & 7);
    const int aCol = (lane >> 4) * 8;
    const int bRow = (lane >> 4) * 8 + (lane & 7);
    const int bCol = ((lane >> 3) & 1) * 8;

    float4 acc[4][4];
#pragma unroll
    for (int i = 0; i < 4; i++)
#pragma unroll
        for (int j = 0; j < 4; j++) acc[i][j] = make_float4(0.f, 0.f, 0.f, 0.f);

    // A chunk: token row r, k = KT + cl*8 -> image (pr*16+i, pc*16+j)
#define PAT_ISSUE(KT, B) do {                                                  \
    _Pragma("unroll")                                                          \
    for (int i2 = 0; i2 < 4; i2++) {                                           \
        int c = tid + i2 * 256;                                                \
        int r = c >> 3, cl = c & 7;                                            \
        int tok = m0 + r;                                                      \
        int k = (KT) + cl * 8;                                                 \
        cp16(ab_u[B] + (r * GPH2 + cl * 8) * 2,                                \
             g_xh + ((tok >> 6) * 16 + (k >> 4)) * 1024                        \
                  + (tok & 63) * 16 + (k & 15));                               \
        cp16(bb_u[B] + (r * GPH2 + cl * 8) * 2,                                \
             g_wph + (n0 + r) * KPATCH + (KT) + cl * 8);                       \
    } } while (0)

    PAT_ISSUE(0, 0);  CP_COMMIT();
    PAT_ISSUE(64, 1); CP_COMMIT();

    const int NIT = KPATCH / 64;   // 4
    for (int it = 0; it < NIT; it++) {
        const int b = it & 1;
        CP_WAIT1();
        __syncthreads();
        const uint32_t Au = ab_u[b];
        const uint32_t Bu = bb_u[b];
#pragma unroll
        for (int gc = 0; gc < 4; gc++) {
            uint32_t af[4][4];
#pragma unroll
            for (int mt = 0; mt < 4; mt++) {
                uint32_t addr = Au + (((wm * 64 + mt * 16 + aRow) * GPH2)
                                      + gc * 16 + aCol) * 2;
                LDSM_X4(af[mt][0], af[mt][1], af[mt][2], af[mt][3], addr);
            }
#pragma unroll
            for (int j = 0; j < 2; j++) {
                uint32_t b0, b1, b2, b3;
                uint32_t addr = Bu + (((wn * 32 + j * 16 + bRow) * GPH2)
                                      + gc * 16 + bCol) * 2;
                LDSM_X4(b0, b1, b2, b3, addr);
#pragma unroll
                for (int mt = 0; mt < 4; mt++) {
                    mma16(acc[mt][2 * j],     af[mt], b0, b1);
                    mma16(acc[mt][2 * j + 1], af[mt], b2, b3);
                }
            }
        }
        __syncthreads();
        if (it + 2 < NIT) PAT_ISSUE((it + 2) * 64, b);
        CP_COMMIT();
    }

#pragma unroll
    for (int nt = 0; nt < 4; nt++) {
        int n = n0 + wn * 32 + nt * 8 + 2 * lj;
        float b0 = bias[n], b1 = bias[n + 1];
#pragma unroll
        for (int mt = 0; mt < 4; mt++) {
            int row = m0 + wm * 64 + mt * 16 + lr;
            *(float2*)&g_tok[row * EMBED + n] =
                make_float2(acc[mt][nt].x + b0, acc[mt][nt].y + b1);
            *(float2*)&g_tok[(row + 8) * EMBED + n] =
                make_float2(acc[mt][nt].z + b0, acc[mt][nt].w + b1);
        }
    }
}

// ============================================================
// Kernel 2: LayerNorm -> fp16 tokens
// ============================================================
__device__ __forceinline__ float block_sum256(float v) {
    __shared__ float sh[8];
    __syncthreads();
    const int lane = threadIdx.x & 31, wrp = threadIdx.x >> 5;
#pragma unroll
    for (int o = 16; o > 0; o >>= 1) v += __shfl_xor_sync(0xffffffffu, v, o);
    if (lane == 0) sh[wrp] = v;
    __syncthreads();
    if (wrp == 0) {
        v = (lane < 8) ? sh[lane] : 0.f;
#pragma unroll
        for (int o = 4; o > 0; o >>= 1) v += __shfl_xor_sync(0xffffffffu, v, o);
        if (lane == 0) sh[0] = v;
    }
    __syncthreads();
    return sh[0];
}

__global__ __launch_bounds__(256) void ln_kernel(
    const float* __restrict__ gamma, const float* __restrict__ beta)
{
    const int n = blockIdx.x;
    const int t = threadIdx.x;
    const float* row = &g_tok[n * EMBED];
    __half* hrow = &g_tok_h[n * EMBED];
    float v0 = row[t], v1 = row[t + 256], v2 = row[t + 512];
    float total = block_sum256(v0 + v1 + v2);
    float mu = total * (1.f / EMBED);
    float d0 = v0 - mu, d1 = v1 - mu, d2 = v2 - mu;
    float tot2 = block_sum256(d0 * d0 + d1 * d1 + d2 * d2);
    float inv = rsqrtf(tot2 * (1.f / EMBED) + 1e-6f);
    hrow[t]       = __float2half(d0 * inv * gamma[t]       + beta[t]);
    hrow[t + 256] = __float2half(d1 * inv * gamma[t + 256] + beta[t + 256]);
    hrow[t + 512] = __float2half(d2 * inv * gamma[t + 512] + beta[t + 512]);
}

// ============================================================
// Kernel 3: QKV GEMM, fp16 mma + ldmatrix, k-tile 64 (unchanged R7)
// ============================================================
__global__ __launch_bounds__(256, 2) void qkv_kernel()
{
    extern __shared__ __half hsm[];
    __half* ab[2] = { hsm,           hsm + GT2 };
    __half* bb[2] = { hsm + 2 * GT2, hsm + 3 * GT2 };
    const uint32_t ab_u[2] = { smem_u32(ab[0]), smem_u32(ab[1]) };
    const uint32_t bb_u[2] = { smem_u32(bb[0]), smem_u32(bb[1]) };

    const int tid = threadIdx.x, wid = tid >> 5, lane = tid & 31;
    const int lj = lane & 3, lr = lane >> 2;
    const int wm = wid >> 2, wn = wid & 3;
    const int m0 = blockIdx.y * 128, n0 = blockIdx.x * 128;

    const int aRow = ((lane >> 3) & 1) * 8 + (lane & 7);
    const int aCol = (lane >> 4) * 8;
    const int bRow = (lane >> 4) * 8 + (lane & 7);
    const int bCol = ((lane >> 3) & 1) * 8;

    float4 acc[4][4];
#pragma unroll
    for (int i = 0; i < 4; i++)
#pragma unroll
        for (int j = 0; j < 4; j++) acc[i][j] = make_float4(0.f, 0.f, 0.f, 0.f);

#define QKV_ISSUE(KT, B) do {                                                  \
    _Pragma("unroll")                                                          \
    for (int i = 0; i < 4; i++) {                                              \
        int c = tid + i * 256;                                                 \
        int r = c >> 3, cl = c & 7;                                            \
        cp16(ab_u[B] + (r * GPH2 + cl * 8) * 2,                                \
             g_tok_h + (m0 + r) * EMBED + (KT) + cl * 8);                      \
        cp16(bb_u[B] + (r * GPH2 + cl * 8) * 2,                                \
             g_wh + (n0 + r) * EMBED + (KT) + cl * 8);                         \
    } } while (0)

    QKV_ISSUE(0, 0);  CP_COMMIT();
    QKV_ISSUE(64, 1); CP_COMMIT();

    const int NIT = EMBED / 64;   // 12
    for (int it = 0; it < NIT; it++) {
        const int b = it & 1;
        CP_WAIT1();
        __syncthreads();
        const uint32_t Au = ab_u[b];
        const uint32_t Bu = bb_u[b];
#pragma unroll
        for (int gc = 0; gc < 4; gc++) {
            uint32_t af[4][4];
#pragma unroll
            for (int mt = 0; mt < 4; mt++) {
                uint32_t addr = Au + (((wm * 64 + mt * 16 + aRow) * GPH2)
                                      + gc * 16 + aCol) * 2;
                LDSM_X4(af[mt][0], af[mt][1], af[mt][2], af[mt][3], addr);
            }
#pragma unroll
            for (int j = 0; j < 2; j++) {
                uint32_t b0, b1, b2, b3;
                uint32_t addr = Bu + (((wn * 32 + j * 16 + bRow) * GPH2)
                                      + gc * 16 + bCol) * 2;
                LDSM_X4(b0, b1, b2, b3, addr);
#pragma unroll
                for (int mt = 0; mt < 4; mt++) {
                    mma16(acc[mt][2 * j],     af[mt], b0, b1);
                    mma16(acc[mt][2 * j + 1], af[mt], b2, b3);
                }
            }
        }
        __syncthreads();
        if (it + 2 < NIT) QKV_ISSUE((it + 2) * 64, b);
        CP_COMMIT();
    }

#pragma unroll
    for (int nt = 0; nt < 4; nt++) {
        int n = n0 + wn * 32 + nt * 8 + 2 * lj;
        int s = n / EMBED;
        int r = n % EMBED;
        int hh = r / DHEAD, dd = r % DHEAD;
#pragma unroll
        for (int mt = 0; mt < 4; mt++) {
            int row = m0 + wm * 64 + mt * 16 + lr;
            if (s < 2) {
                __half* dst = ((s == 0) ? g_qh : g_kh)
                            + (hh * N_TOK + row) * DHEAD + dd;
                *(__half2*)dst = __floats2half2_rn(acc[mt][nt].x, acc[mt][nt].y);
                *(__half2*)(dst + 8 * DHEAD) =
                    __floats2half2_rn(acc[mt][nt].z, acc[mt][nt].w);
            } else {
                __half* dst = g_vt + (hh * DHEAD + dd) * N_TOK + row;
                dst[0]          = __float2half(acc[mt][nt].x);
                dst[N_TOK]      = __float2half(acc[mt][nt].y);
                dst[8]          = __float2half(acc[mt][nt].z);
                dst[N_TOK + 8]  = __float2half(acc[mt][nt].w);
            }
        }
    }
}

// ============================================================
// Kernel 4: flash attention, fp16 mma + ldmatrix.
// CTA = (head, 128 q), 4 warps x 2 m-tiles (32 rows each): every
// K/V LDSM fragment feeds TWO mma chains -> half the shared-load
// pressure per flop. l via FADD (fma pipe idle). 3 CTAs/SM.
// ============================================================
#define AQ   128
#define AKV  64
#define KPITCH 72
#define ATILEH (AKV * KPITCH)
#define ATH  128

__global__ __launch_bounds__(ATH, 3) void attn_kernel(float* __restrict__ out)
{
    __shared__ __half hsm[4 * ATILEH];           // 36,864 B
    __half* kb[2] = { hsm,              hsm + ATILEH };
    __half* vb[2] = { hsm + 2 * ATILEH, hsm + 3 * ATILEH };
    const uint32_t kb_u[2] = { smem_u32(kb[0]), smem_u32(kb[1]) };
    const uint32_t vb_u[2] = { smem_u32(vb[0]), smem_u32(vb[1]) };

    const int tid = threadIdx.x, wid = tid >> 5, lane = tid & 31;
    const int lj = lane & 3, lr = lane >> 2;
    const int h = blockIdx.y, q0 = blockIdx.x * AQ;

    const int bRow = (lane >> 4) * 8 + (lane & 7);
    const int bCol = ((lane >> 3) & 1) * 8;

    const __half* Kh  = g_kh + h * N_TOK * DHEAD;
    const __half* Vth = g_vt + h * DHEAD * N_TOK;

    // Q fragments: 2 m-tiles of 16 rows per warp
    uint32_t qa[2][4][4];
#pragma unroll
    for (int mt = 0; mt < 2; mt++) {
        const __half* Q0 = g_qh
            + (h * N_TOK + q0 + wid * 32 + mt * 16 + lr) * DHEAD;
#pragma unroll
        for (int gc = 0; gc < 4; gc++) {
            int base = gc * 16 + 2 * lj;
            qa[mt][gc][0] = ldh2(Q0 + base);
            qa[mt][gc][1] = ldh2(Q0 + 8 * DHEAD + base);
            qa[mt][gc][2] = ldh2(Q0 + base + 8);
            qa[mt][gc][3] = ldh2(Q0 + 8 * DHEAD + base + 8);
        }
    }

    float4 oacc[2][8];
#pragma unroll
    for (int mt = 0; mt < 2; mt++)
#pragma unroll
        for (int i = 0; i < 8; i++) oacc[mt][i] = make_float4(0.f, 0.f, 0.f, 0.f);
    float l_lo[2] = {0.f, 0.f}, l_hi[2] = {0.f, 0.f};

    // K tile: 64 rows x 64 halves = 8 chunks/row -> 512; V^T same.
#define ATT_ISSUE(T, B) do {                                                   \
    _Pragma("unroll")                                                          \
    for (int i = 0; i < 4; i++) {                                              \
        int c = tid + i * ATH;                                                 \
        int r = c >> 3, cl = c & 7;                                            \
        cp16(kb_u[B] + (r * KPITCH + cl * 8) * 2,                              \
             Kh + ((T) * AKV + r) * DHEAD + cl * 8);                           \
        cp16(vb_u[B] + (r * KPITCH + cl * 8) * 2,                              \
             Vth + r * N_TOK + (T) * AKV + cl * 8);                            \
    } } while (0)

    ATT_ISSUE(0, 0); CP_COMMIT();
    ATT_ISSUE(1, 1); CP_COMMIT();

    const int NT = N_TOK / AKV;   // 64
    for (int t = 0; t < NT; t++) {
        const int b = t & 1;
        CP_WAIT1();
        __syncthreads();
        const uint32_t Ku = kb_u[b];
        const uint32_t Vu = vb_u[b];

#pragma unroll
        for (int pair = 0; pair < 4; pair++) {    // 16-kv chunk
            float4 s[2][2];
#pragma unroll
            for (int mt = 0; mt < 2; mt++) {
                s[mt][0] = make_float4(0.f, 0.f, 0.f, 0.f);
                s[mt][1] = make_float4(0.f, 0.f, 0.f, 0.f);
            }
#pragma unroll
            for (int gc = 0; gc < 4; gc++) {
                uint32_t k0, k1, k2, k3;
                uint32_t addr = Ku + (((pair * 16 + bRow) * KPITCH)
                                      + gc * 16 + bCol) * 2;
                LDSM_X4(k0, k1, k2, k3, addr);
#pragma unroll
                for (int mt = 0; mt < 2; mt++) {
                    mma16(s[mt][0], qa[mt][gc], k0, k1);
                    mma16(s[mt][1], qa[mt][gc], k2, k3);
                }
            }
            uint32_t pa[2][4];
#pragma unroll
            for (int mt = 0; mt < 2; mt++) {
                float p0 = __expf(s[mt][0].x * 0.125f);
                float p1 = __expf(s[mt][0].y * 0.125f);
                float p2 = __expf(s[mt][0].z * 0.125f);
                float p3 = __expf(s[mt][0].w * 0.125f);
                float p4 = __expf(s[mt][1].x * 0.125f);
                float p5 = __expf(s[mt][1].y * 0.125f);
                float p6 = __expf(s[mt][1].z * 0.125f);
                float p7 = __expf(s[mt][1].w * 0.125f);
                l_lo[mt] += p0 + p1 + p4 + p5;
                l_hi[mt] += p2 + p3 + p6 + p7;
                pa[mt][0] = packh2(p0, p1); pa[mt][1] = packh2(p2, p3);
                pa[mt][2] = packh2(p4, p5); pa[mt][3] = packh2(p6, p7);
            }
#pragma unroll
            for (int dtj = 0; dtj < 4; dtj++) {
                uint32_t v0, v1, v2, v3;
                uint32_t addr = Vu + (((dtj * 16 + bRow) * KPITCH)
                                      + pair * 16 + bCol) * 2;
                LDSM_X4(v0, v1, v2, v3, addr);
#pragma unroll
                for (int mt = 0; mt < 2; mt++) {
                    mma16(oacc[mt][2 * dtj],     pa[mt], v0, v1);
                    mma16(oacc[mt][2 * dtj + 1], pa[mt], v2, v3);
                }
            }
        }

        __syncthreads();
        if (t + 2 < NT) ATT_ISSUE(t + 2, b);
        CP_COMMIT();
    }

    // ---- epilogue: quad-reduce l, normalize, store ----
#pragma unroll
    for (int mt = 0; mt < 2; mt++) {
        float llo = l_lo[mt], lhi = l_hi[mt];
        llo += __shfl_xor_sync(0xffffffffu, llo, 1);
        llo += __shfl_xor_sync(0xffffffffu, llo, 2);
        lhi += __shfl_xor_sync(0xffffffffu, lhi, 1);
        lhi += __shfl_xor_sync(0xffffffffu, lhi, 2);
        const float inv_lo = 1.f / llo;
        const float inv_hi = 1.f / lhi;
        const int row = q0 + wid * 32 + mt * 16 + lr;
        float* o0 = out + row * EMBED + h * DHEAD + 2 * lj;
        float* o8 = o0 + 8 * EMBED;
#pragma unroll
        for (int dt = 0; dt < 8; dt++) {
            *(float2*)(o0 + dt * 8) = make_float2(oacc[mt][dt].x * inv_lo,
                                                  oacc[mt][dt].y * inv_lo);
            *(float2*)(o8 + dt * 8) = make_float2(oacc[mt][dt].z * inv_hi,
                                                  oacc[mt][dt].w * inv_hi);
        }
    }
}

// ============================================================
extern "C" void kernel_launch(void* const* d_in, const int* in_sizes, int n_in,
                              void* d_out, int out_size)
{
    const float* x  = (const float*)d_in[0];
    const float* pw = (const float*)d_in[1];
    const float* pb = (const float*)d_in[2];
    const float* lg = (const float*)d_in[3];
    const float* lb = (const float*)d_in[4];
    const float* qw = (const float*)d_in[5];
    float* out = (float*)d_out;

    cudaFuncSetAttribute(qkv_kernel,
                         cudaFuncAttributeMaxDynamicSharedMemorySize, GEMM_SMEM);
    cudaFuncSetAttribute(patch_mma_kernel,
                         cudaFuncAttributeMaxDynamicSharedMemorySize, GEMM_SMEM);

    xcvt_kernel<<<1024, 256>>>(x);
    wpcvt_kernel<<<(EMBED * KPATCH) / 1024, 256>>>(pw);
    wcvt_kernel<<<(3 * EMBED * EMBED) / 1024, 256>>>(qw);
    patch_mma_kernel<<<dim3(EMBED / 128, N_TOK / 128), 256, GEMM_SMEM>>>(pb);
    ln_kernel<<<N_TOK, 256>>>(lg, lb);
    qkv_kernel<<<dim3(2304 / 128, N_TOK / 128), 256, GEMM_SMEM>>>();
    attn_kernel<<<dim3(N_TOK / AQ, NHEAD), ATH>>>(out);
}

// round 9
// speedup vs baseline: 2.8973x; 1.1107x over previous
#include <cuda_runtime.h>
#include <cuda_fp16.h>
#include <cstdint>
#include <math.h>

#define N_TOK  4096
#define EMBED  768
#define NHEAD  12
#define DHEAD  64
#define KPATCH 256

// ---- device scratch (allocation-free: module globals) ----
__device__ float  g_tok[N_TOK * EMBED];          // post patch-embed (fp32)
__device__ __half g_tok_h[N_TOK * EMBED];        // post-LN tokens (fp16)
__device__ __half g_xh[1024 * 1024];             // image (fp16)
__device__ __half g_wph[EMBED * KPATCH];         // patch weight (fp16)
__device__ __half g_wh[3 * EMBED * EMBED];       // qkv weight (fp16)
__device__ __half g_qh[NHEAD * N_TOK * DHEAD];   // [h, n, d]
__device__ __half g_kh[NHEAD * N_TOK * DHEAD];   // [h, n, d]
__device__ __half g_vt[NHEAD * DHEAD * N_TOK];   // [h, d, n]  (V transposed)

// ============================================================
// helpers
// ============================================================
__device__ __forceinline__ uint32_t smem_u32(const void* p) {
    uint32_t a;
    asm("{ .reg .u64 t; cvta.to.shared.u64 t, %1; cvt.u32.u64 %0, t; }"
        : "=r"(a) : "l"(p));
    return a;
}
__device__ __forceinline__ void cp16(uint32_t dst, const void* src) {
    asm volatile("cp.async.cg.shared.global [%0], [%1], 16;"
                 :: "r"(dst), "l"(src));
}
#define CP_COMMIT() asm volatile("cp.async.commit_group;" ::: "memory")
#define CP_WAIT1()  asm volatile("cp.async.wait_group 1;" ::: "memory")

// m16n8k16 fp16 mma, fp32 accumulate
__device__ __forceinline__ void mma16(float4& d, const uint32_t a[4],
                                      uint32_t b0, uint32_t b1) {
    asm volatile(
        "mma.sync.aligned.m16n8k16.row.col.f32.f16.f16.f32 "
        "{%0,%1,%2,%3}, {%4,%5,%6,%7}, {%8,%9}, {%0,%1,%2,%3};"
        : "+f"(d.x), "+f"(d.y), "+f"(d.z), "+f"(d.w)
        : "r"(a[0]), "r"(a[1]), "r"(a[2]), "r"(a[3]), "r"(b0), "r"(b1));
}
#define LDSM_X4(r0, r1, r2, r3, addr) \
    asm volatile("ldmatrix.sync.aligned.m8n8.x4.shared.b16 {%0,%1,%2,%3}, [%4];" \
        : "=r"(r0), "=r"(r1), "=r"(r2), "=r"(r3) : "r"(addr))

__device__ __forceinline__ uint32_t ldh2(const __half* p) {
    return *reinterpret_cast<const uint32_t*>(p);
}
__device__ __forceinline__ uint32_t packh2(float lo, float hi) {
    __half2 h = __floats2half2_rn(lo, hi);
    return *reinterpret_cast<uint32_t*>(&h);
}
// exp2 on a packed half2 via single MUFU op
__device__ __forceinline__ void h2exp2(uint32_t& v) {
    asm("ex2.approx.f16x2 %0, %0;" : "+r"(v));
}

// ============================================================
// converters: image / patch-weight / qkv-weight  fp32 -> fp16
// ============================================================
__global__ __launch_bounds__(256) void xcvt_kernel(const float* __restrict__ x)
{
    int i = (blockIdx.x * 256 + threadIdx.x) * 4;
    float4 v = *(const float4*)(x + i);
    __half2* dst = (__half2*)(g_xh + i);
    dst[0] = __floats2half2_rn(v.x, v.y);
    dst[1] = __floats2half2_rn(v.z, v.w);
}
__global__ __launch_bounds__(256) void wpcvt_kernel(const float* __restrict__ w)
{
    int i = (blockIdx.x * 256 + threadIdx.x) * 4;
    float4 v = *(const float4*)(w + i);
    __half2* dst = (__half2*)(g_wph + i);
    dst[0] = __floats2half2_rn(v.x, v.y);
    dst[1] = __floats2half2_rn(v.z, v.w);
}
__global__ __launch_bounds__(256) void wcvt_kernel(const float* __restrict__ w)
{
    int i = (blockIdx.x * 256 + threadIdx.x) * 4;
    float4 v = *(const float4*)(w + i);
    __half2* dst = (__half2*)(g_wh + i);
    dst[0] = __floats2half2_rn(v.x, v.y);
    dst[1] = __floats2half2_rn(v.z, v.w);
}

// ============================================================
// smem geometry shared by GEMM kernels
// ============================================================
#define GPH2 72                       // smem pitch in halves (144B)
#define GT2  (128 * GPH2)
#define GEMM_SMEM (4 * GT2 * 2)       // 73728 B

// ============================================================
// Kernel 1: patch-embed GEMM, fp16 mma (unchanged R8)
// ============================================================
__global__ __launch_bounds__(256, 2) void patch_mma_kernel(
    const float* __restrict__ bias)
{
    extern __shared__ __half hsm[];
    __half* ab[2] = { hsm,           hsm + GT2 };
    __half* bb[2] = { hsm + 2 * GT2, hsm + 3 * GT2 };
    const uint32_t ab_u[2] = { smem_u32(ab[0]), smem_u32(ab[1]) };
    const uint32_t bb_u[2] = { smem_u32(bb[0]), smem_u32(bb[1]) };

    const int tid = threadIdx.x, wid = tid >> 5, lane = tid & 31;
    const int lj = lane & 3, lr = lane >> 2;
    const int wm = wid >> 2, wn = wid & 3;
    const int m0 = blockIdx.y * 128, n0 = blockIdx.x * 128;

    const int aRow = ((lane >> 3) & 1) * 8 + (lane & 7);
    const int aCol = (lane >> 4) * 8;
    const int bRow = (lane >> 4) * 8 + (lane & 7);
    const int bCol = ((lane >> 3) & 1) * 8;

    float4 acc[4][4];
#pragma unroll
    for (int i = 0; i < 4; i++)
#pragma unroll
        for (int j = 0; j < 4; j++) acc[i][j] = make_float4(0.f, 0.f, 0.f, 0.f);

#define PAT_ISSUE(KT, B) do {                                                  \
    _Pragma("unroll")                                                          \
    for (int i2 = 0; i2 < 4; i2++) {                                           \
        int c = tid + i2 * 256;                                                \
        int r = c >> 3, cl = c & 7;                                            \
        int tok = m0 + r;                                                      \
        int k = (KT) + cl * 8;                                                 \
        cp16(ab_u[B] + (r * GPH2 + cl * 8) * 2,                                \
             g_xh + ((tok >> 6) * 16 + (k >> 4)) * 1024                        \
                  + (tok & 63) * 16 + (k & 15));                               \
        cp16(bb_u[B] + (r * GPH2 + cl * 8) * 2,                                \
             g_wph + (n0 + r) * KPATCH + (KT) + cl * 8);                       \
    } } while (0)

    PAT_ISSUE(0, 0);  CP_COMMIT();
    PAT_ISSUE(64, 1); CP_COMMIT();

    const int NIT = KPATCH / 64;   // 4
    for (int it = 0; it < NIT; it++) {
        const int b = it & 1;
        CP_WAIT1();
        __syncthreads();
        const uint32_t Au = ab_u[b];
        const uint32_t Bu = bb_u[b];
#pragma unroll
        for (int gc = 0; gc < 4; gc++) {
            uint32_t af[4][4];
#pragma unroll
            for (int mt = 0; mt < 4; mt++) {
                uint32_t addr = Au + (((wm * 64 + mt * 16 + aRow) * GPH2)
                                      + gc * 16 + aCol) * 2;
                LDSM_X4(af[mt][0], af[mt][1], af[mt][2], af[mt][3], addr);
            }
#pragma unroll
            for (int j = 0; j < 2; j++) {
                uint32_t b0, b1, b2, b3;
                uint32_t addr = Bu + (((wn * 32 + j * 16 + bRow) * GPH2)
                                      + gc * 16 + bCol) * 2;
                LDSM_X4(b0, b1, b2, b3, addr);
#pragma unroll
                for (int mt = 0; mt < 4; mt++) {
                    mma16(acc[mt][2 * j],     af[mt], b0, b1);
                    mma16(acc[mt][2 * j + 1], af[mt], b2, b3);
                }
            }
        }
        __syncthreads();
        if (it + 2 < NIT) PAT_ISSUE((it + 2) * 64, b);
        CP_COMMIT();
    }

#pragma unroll
    for (int nt = 0; nt < 4; nt++) {
        int n = n0 + wn * 32 + nt * 8 + 2 * lj;
        float b0 = bias[n], b1 = bias[n + 1];
#pragma unroll
        for (int mt = 0; mt < 4; mt++) {
            int row = m0 + wm * 64 + mt * 16 + lr;
            *(float2*)&g_tok[row * EMBED + n] =
                make_float2(acc[mt][nt].x + b0, acc[mt][nt].y + b1);
            *(float2*)&g_tok[(row + 8) * EMBED + n] =
                make_float2(acc[mt][nt].z + b0, acc[mt][nt].w + b1);
        }
    }
}

// ============================================================
// Kernel 2: LayerNorm -> fp16 tokens
// ============================================================
__device__ __forceinline__ float block_sum256(float v) {
    __shared__ float sh[8];
    __syncthreads();
    const int lane = threadIdx.x & 31, wrp = threadIdx.x >> 5;
#pragma unroll
    for (int o = 16; o > 0; o >>= 1) v += __shfl_xor_sync(0xffffffffu, v, o);
    if (lane == 0) sh[wrp] = v;
    __syncthreads();
    if (wrp == 0) {
        v = (lane < 8) ? sh[lane] : 0.f;
#pragma unroll
        for (int o = 4; o > 0; o >>= 1) v += __shfl_xor_sync(0xffffffffu, v, o);
        if (lane == 0) sh[0] = v;
    }
    __syncthreads();
    return sh[0];
}

__global__ __launch_bounds__(256) void ln_kernel(
    const float* __restrict__ gamma, const float* __restrict__ beta)
{
    const int n = blockIdx.x;
    const int t = threadIdx.x;
    const float* row = &g_tok[n * EMBED];
    __half* hrow = &g_tok_h[n * EMBED];
    float v0 = row[t], v1 = row[t + 256], v2 = row[t + 512];
    float total = block_sum256(v0 + v1 + v2);
    float mu = total * (1.f / EMBED);
    float d0 = v0 - mu, d1 = v1 - mu, d2 = v2 - mu;
    float tot2 = block_sum256(d0 * d0 + d1 * d1 + d2 * d2);
    float inv = rsqrtf(tot2 * (1.f / EMBED) + 1e-6f);
    hrow[t]       = __float2half(d0 * inv * gamma[t]       + beta[t]);
    hrow[t + 256] = __float2half(d1 * inv * gamma[t + 256] + beta[t + 256]);
    hrow[t + 512] = __float2half(d2 * inv * gamma[t + 512] + beta[t + 512]);
}

// ============================================================
// Kernel 3: QKV GEMM, fp16 mma + ldmatrix, k-tile 64 (unchanged R7)
// ============================================================
__global__ __launch_bounds__(256, 2) void qkv_kernel()
{
    extern __shared__ __half hsm[];
    __half* ab[2] = { hsm,           hsm + GT2 };
    __half* bb[2] = { hsm + 2 * GT2, hsm + 3 * GT2 };
    const uint32_t ab_u[2] = { smem_u32(ab[0]), smem_u32(ab[1]) };
    const uint32_t bb_u[2] = { smem_u32(bb[0]), smem_u32(bb[1]) };

    const int tid = threadIdx.x, wid = tid >> 5, lane = tid & 31;
    const int lj = lane & 3, lr = lane >> 2;
    const int wm = wid >> 2, wn = wid & 3;
    const int m0 = blockIdx.y * 128, n0 = blockIdx.x * 128;

    const int aRow = ((lane >> 3) & 1) * 8 + (lane & 7);
    const int aCol = (lane >> 4) * 8;
    const int bRow = (lane >> 4) * 8 + (lane & 7);
    const int bCol = ((lane >> 3) & 1) * 8;

    float4 acc[4][4];
#pragma unroll
    for (int i = 0; i < 4; i++)
#pragma unroll
        for (int j = 0; j < 4; j++) acc[i][j] = make_float4(0.f, 0.f, 0.f, 0.f);

#define QKV_ISSUE(KT, B) do {                                                  \
    _Pragma("unroll")                                                          \
    for (int i = 0; i < 4; i++) {                                              \
        int c = tid + i * 256;                                                 \
        int r = c >> 3, cl = c & 7;                                            \
        cp16(ab_u[B] + (r * GPH2 + cl * 8) * 2,                                \
             g_tok_h + (m0 + r) * EMBED + (KT) + cl * 8);                      \
        cp16(bb_u[B] + (r * GPH2 + cl * 8) * 2,                                \
             g_wh + (n0 + r) * EMBED + (KT) + cl * 8);                         \
    } } while (0)

    QKV_ISSUE(0, 0);  CP_COMMIT();
    QKV_ISSUE(64, 1); CP_COMMIT();

    const int NIT = EMBED / 64;   // 12
    for (int it = 0; it < NIT; it++) {
        const int b = it & 1;
        CP_WAIT1();
        __syncthreads();
        const uint32_t Au = ab_u[b];
        const uint32_t Bu = bb_u[b];
#pragma unroll
        for (int gc = 0; gc < 4; gc++) {
            uint32_t af[4][4];
#pragma unroll
            for (int mt = 0; mt < 4; mt++) {
                uint32_t addr = Au + (((wm * 64 + mt * 16 + aRow) * GPH2)
                                      + gc * 16 + aCol) * 2;
                LDSM_X4(af[mt][0], af[mt][1], af[mt][2], af[mt][3], addr);
            }
#pragma unroll
            for (int j = 0; j < 2; j++) {
                uint32_t b0, b1, b2, b3;
                uint32_t addr = Bu + (((wn * 32 + j * 16 + bRow) * GPH2)
                                      + gc * 16 + bCol) * 2;
                LDSM_X4(b0, b1, b2, b3, addr);
#pragma unroll
                for (int mt = 0; mt < 4; mt++) {
                    mma16(acc[mt][2 * j],     af[mt], b0, b1);
                    mma16(acc[mt][2 * j + 1], af[mt], b2, b3);
                }
            }
        }
        __syncthreads();
        if (it + 2 < NIT) QKV_ISSUE((it + 2) * 64, b);
        CP_COMMIT();
    }

#pragma unroll
    for (int nt = 0; nt < 4; nt++) {
        int n = n0 + wn * 32 + nt * 8 + 2 * lj;
        int s = n / EMBED;
        int r = n % EMBED;
        int hh = r / DHEAD, dd = r % DHEAD;
#pragma unroll
        for (int mt = 0; mt < 4; mt++) {
            int row = m0 + wm * 64 + mt * 16 + lr;
            if (s < 2) {
                __half* dst = ((s == 0) ? g_qh : g_kh)
                            + (hh * N_TOK + row) * DHEAD + dd;
                *(__half2*)dst = __floats2half2_rn(acc[mt][nt].x, acc[mt][nt].y);
                *(__half2*)(dst + 8 * DHEAD) =
                    __floats2half2_rn(acc[mt][nt].z, acc[mt][nt].w);
            } else {
                __half* dst = g_vt + (hh * DHEAD + dd) * N_TOK + row;
                dst[0]          = __float2half(acc[mt][nt].x);
                dst[N_TOK]      = __float2half(acc[mt][nt].y);
                dst[8]          = __float2half(acc[mt][nt].z);
                dst[N_TOK + 8]  = __float2half(acc[mt][nt].w);
            }
        }
    }
}

// ============================================================
// Kernel 4: flash attention, fp16 mma + ldmatrix.
// CTA = (head, 128 q), 4 warps x 2 m-tiles. Softmax exp via
// ex2.approx.f16x2 (half the MUFU ops); its output IS the PV A-frag.
// l via ones-column mma -> consistent with fp16 P. 3 CTAs/SM.
// ============================================================
#define AQ   128
#define AKV  64
#define KPITCH 72
#define ATILEH (AKV * KPITCH)
#define ATH  128

__global__ __launch_bounds__(ATH, 3) void attn_kernel(float* __restrict__ out)
{
    __shared__ __half hsm[4 * ATILEH];           // 36,864 B
    __half* kb[2] = { hsm,              hsm + ATILEH };
    __half* vb[2] = { hsm + 2 * ATILEH, hsm + 3 * ATILEH };
    const uint32_t kb_u[2] = { smem_u32(kb[0]), smem_u32(kb[1]) };
    const uint32_t vb_u[2] = { smem_u32(vb[0]), smem_u32(vb[1]) };

    const int tid = threadIdx.x, wid = tid >> 5, lane = tid & 31;
    const int lj = lane & 3, lr = lane >> 2;
    const int h = blockIdx.y, q0 = blockIdx.x * AQ;

    const int bRow = (lane >> 4) * 8 + (lane & 7);
    const int bCol = ((lane >> 3) & 1) * 8;
    const uint32_t ONEH2 = 0x3C003C00u;
    const float CEXP = 0.180336880f;   // 0.125 * log2(e)

    const __half* Kh  = g_kh + h * N_TOK * DHEAD;
    const __half* Vth = g_vt + h * DHEAD * N_TOK;

    // Q fragments: 2 m-tiles of 16 rows per warp
    uint32_t qa[2][4][4];
#pragma unroll
    for (int mt = 0; mt < 2; mt++) {
        const __half* Q0 = g_qh
            + (h * N_TOK + q0 + wid * 32 + mt * 16 + lr) * DHEAD;
#pragma unroll
        for (int gc = 0; gc < 4; gc++) {
            int base = gc * 16 + 2 * lj;
            qa[mt][gc][0] = ldh2(Q0 + base);
            qa[mt][gc][1] = ldh2(Q0 + 8 * DHEAD + base);
            qa[mt][gc][2] = ldh2(Q0 + base + 8);
            qa[mt][gc][3] = ldh2(Q0 + 8 * DHEAD + base + 8);
        }
    }

    float4 oacc[2][8];
#pragma unroll
    for (int mt = 0; mt < 2; mt++)
#pragma unroll
        for (int i = 0; i < 8; i++) oacc[mt][i] = make_float4(0.f, 0.f, 0.f, 0.f);
    float4 lacc[2];
    lacc[0] = make_float4(0.f, 0.f, 0.f, 0.f);
    lacc[1] = make_float4(0.f, 0.f, 0.f, 0.f);

#define ATT_ISSUE(T, B) do {                                                   \
    _Pragma("unroll")                                                          \
    for (int i = 0; i < 4; i++) {                                              \
        int c = tid + i * ATH;                                                 \
        int r = c >> 3, cl = c & 7;                                            \
        cp16(kb_u[B] + (r * KPITCH + cl * 8) * 2,                              \
             Kh + ((T) * AKV + r) * DHEAD + cl * 8);                           \
        cp16(vb_u[B] + (r * KPITCH + cl * 8) * 2,                              \
             Vth + r * N_TOK + (T) * AKV + cl * 8);                            \
    } } while (0)

    ATT_ISSUE(0, 0); CP_COMMIT();
    ATT_ISSUE(1, 1); CP_COMMIT();

    const int NT = N_TOK / AKV;   // 64
    for (int t = 0; t < NT; t++) {
        const int b = t & 1;
        CP_WAIT1();
        __syncthreads();
        const uint32_t Ku = kb_u[b];
        const uint32_t Vu = vb_u[b];

#pragma unroll
        for (int pair = 0; pair < 4; pair++) {    // 16-kv chunk
            float4 s[2][2];
#pragma unroll
            for (int mt = 0; mt < 2; mt++) {
                s[mt][0] = make_float4(0.f, 0.f, 0.f, 0.f);
                s[mt][1] = make_float4(0.f, 0.f, 0.f, 0.f);
            }
#pragma unroll
            for (int gc = 0; gc < 4; gc++) {
                uint32_t k0, k1, k2, k3;
                uint32_t addr = Ku + (((pair * 16 + bRow) * KPITCH)
                                      + gc * 16 + bCol) * 2;
                LDSM_X4(k0, k1, k2, k3, addr);
#pragma unroll
                for (int mt = 0; mt < 2; mt++) {
                    mma16(s[mt][0], qa[mt][gc], k0, k1);
                    mma16(s[mt][1], qa[mt][gc], k2, k3);
                }
            }
            // exp2 in f16x2: pa = exp(s/8), one MUFU per two values
            uint32_t pa[2][4];
#pragma unroll
            for (int mt = 0; mt < 2; mt++) {
                pa[mt][0] = packh2(s[mt][0].x * CEXP, s[mt][0].y * CEXP);
                pa[mt][1] = packh2(s[mt][0].z * CEXP, s[mt][0].w * CEXP);
                pa[mt][2] = packh2(s[mt][1].x * CEXP, s[mt][1].y * CEXP);
                pa[mt][3] = packh2(s[mt][1].z * CEXP, s[mt][1].w * CEXP);
                h2exp2(pa[mt][0]); h2exp2(pa[mt][1]);
                h2exp2(pa[mt][2]); h2exp2(pa[mt][3]);
            }
#pragma unroll
            for (int dtj = 0; dtj < 4; dtj++) {
                uint32_t v0, v1, v2, v3;
                uint32_t addr = Vu + (((dtj * 16 + bRow) * KPITCH)
                                      + pair * 16 + bCol) * 2;
                LDSM_X4(v0, v1, v2, v3, addr);
#pragma unroll
                for (int mt = 0; mt < 2; mt++) {
                    mma16(oacc[mt][2 * dtj],     pa[mt], v0, v1);
                    mma16(oacc[mt][2 * dtj + 1], pa[mt], v2, v3);
                }
            }
            mma16(lacc[0], pa[0], ONEH2, ONEH2);   // l = row-sum of P
            mma16(lacc[1], pa[1], ONEH2, ONEH2);
        }

        __syncthreads();
        if (t + 2 < NT) ATT_ISSUE(t + 2, b);
        CP_COMMIT();
    }

    // ---- epilogue: l straight from lacc (no shuffles) ----
#pragma unroll
    for (int mt = 0; mt < 2; mt++) {
        const float inv_lo = 1.f / lacc[mt].x;
        const float inv_hi = 1.f / lacc[mt].z;
        const int row = q0 + wid * 32 + mt * 16 + lr;
        float* o0 = out + row * EMBED + h * DHEAD + 2 * lj;
        float* o8 = o0 + 8 * EMBED;
#pragma unroll
        for (int dt = 0; dt < 8; dt++) {
            *(float2*)(o0 + dt * 8) = make_float2(oacc[mt][dt].x * inv_lo,
                                                  oacc[mt][dt].y * inv_lo);
            *(float2*)(o8 + dt * 8) = make_float2(oacc[mt][dt].z * inv_hi,
                                                  oacc[mt][dt].w * inv_hi);
        }
    }
}

// ============================================================
extern "C" void kernel_launch(void* const* d_in, const int* in_sizes, int n_in,
                              void* d_out, int out_size)
{
    const float* x  = (const float*)d_in[0];
    const float* pw = (const float*)d_in[1];
    const float* pb = (const float*)d_in[2];
    const float* lg = (const float*)d_in[3];
    const float* lb = (const float*)d_in[4];
    const float* qw = (const float*)d_in[5];
    float* out = (float*)d_out;

    cudaFuncSetAttribute(qkv_kernel,
                         cudaFuncAttributeMaxDynamicSharedMemorySize, GEMM_SMEM);
    cudaFuncSetAttribute(patch_mma_kernel,
                         cudaFuncAttributeMaxDynamicSharedMemorySize, GEMM_SMEM);

    xcvt_kernel<<<1024, 256>>>(x);
    wpcvt_kernel<<<(EMBED * KPATCH) / 1024, 256>>>(pw);
    wcvt_kernel<<<(3 * EMBED * EMBED) / 1024, 256>>>(qw);
    patch_mma_kernel<<<dim3(EMBED / 128, N_TOK / 128), 256, GEMM_SMEM>>>(pb);
    ln_kernel<<<N_TOK, 256>>>(lg, lb);
    qkv_kernel<<<dim3(2304 / 128, N_TOK / 128), 256, GEMM_SMEM>>>();
    attn_kernel<<<dim3(N_TOK / AQ, NHEAD), ATH>>>(out);
}

// round 10
// speedup vs baseline: 2.9865x; 1.0308x over previous
#include <cuda_runtime.h>
#include <cuda_fp16.h>
#include <cstdint>
#include <math.h>

#define N_TOK  4096
#define EMBED  768
#define NHEAD  12
#define DHEAD  64
#define KPATCH 256

// ---- device scratch (allocation-free: module globals) ----
__device__ float  g_tok[N_TOK * EMBED];          // post patch-embed (fp32)
__device__ __half g_tok_h[N_TOK * EMBED];        // post-LN tokens (fp16)
__device__ __half g_xh[1024 * 1024];             // image (fp16)
__device__ __half g_wph[EMBED * KPATCH];         // patch weight (fp16)
__device__ __half g_wh[3 * EMBED * EMBED];       // qkv weight (fp16)
__device__ __half g_qh[NHEAD * N_TOK * DHEAD];   // [h, n, d]
__device__ __half g_kh[NHEAD * N_TOK * DHEAD];   // [h, n, d]
__device__ __half g_vt[NHEAD * DHEAD * N_TOK];   // [h, d, n]  (V transposed)

// ============================================================
// helpers
// ============================================================
__device__ __forceinline__ uint32_t smem_u32(const void* p) {
    uint32_t a;
    asm("{ .reg .u64 t; cvta.to.shared.u64 t, %1; cvt.u32.u64 %0, t; }"
        : "=r"(a) : "l"(p));
    return a;
}
__device__ __forceinline__ void cp16(uint32_t dst, const void* src) {
    asm volatile("cp.async.cg.shared.global [%0], [%1], 16;"
                 :: "r"(dst), "l"(src));
}
#define CP_COMMIT() asm volatile("cp.async.commit_group;" ::: "memory")
#define CP_WAIT1()  asm volatile("cp.async.wait_group 1;" ::: "memory")

// m16n8k16 fp16 mma, fp32 accumulate
__device__ __forceinline__ void mma16(float4& d, const uint32_t a[4],
                                      uint32_t b0, uint32_t b1) {
    asm volatile(
        "mma.sync.aligned.m16n8k16.row.col.f32.f16.f16.f32 "
        "{%0,%1,%2,%3}, {%4,%5,%6,%7}, {%8,%9}, {%0,%1,%2,%3};"
        : "+f"(d.x), "+f"(d.y), "+f"(d.z), "+f"(d.w)
        : "r"(a[0]), "r"(a[1]), "r"(a[2]), "r"(a[3]), "r"(b0), "r"(b1));
}
// m16n8k16 fp16 mma, fp16 accumulate (full rate)
__device__ __forceinline__ void mma16h(uint32_t& d0, uint32_t& d1,
                                       const uint32_t a[4],
                                       uint32_t b0, uint32_t b1) {
    asm volatile(
        "mma.sync.aligned.m16n8k16.row.col.f16.f16.f16.f16 "
        "{%0,%1}, {%2,%3,%4,%5}, {%6,%7}, {%0,%1};"
        : "+r"(d0), "+r"(d1)
        : "r"(a[0]), "r"(a[1]), "r"(a[2]), "r"(a[3]), "r"(b0), "r"(b1));
}
#define LDSM_X4(r0, r1, r2, r3, addr) \
    asm volatile("ldmatrix.sync.aligned.m8n8.x4.shared.b16 {%0,%1,%2,%3}, [%4];" \
        : "=r"(r0), "=r"(r1), "=r"(r2), "=r"(r3) : "r"(addr))

__device__ __forceinline__ uint32_t ldh2(const __half* p) {
    return *reinterpret_cast<const uint32_t*>(p);
}
// exp2 on a packed half2 via single MUFU op
__device__ __forceinline__ void h2exp2(uint32_t& v) {
    asm("ex2.approx.f16x2 %0, %0;" : "+r"(v));
}
__device__ __forceinline__ uint32_t h2mul(uint32_t a, uint32_t b) {
    uint32_t r;
    asm("mul.f16x2 %0, %1, %2;" : "=r"(r) : "r"(a), "r"(b));
    return r;
}

// ============================================================
// merged converter: image | patch-weight | qkv-weight  fp32 -> fp16
// chunk layout: [0,1024) img, [1024,1216) wp, [1216,2944) wq
// ============================================================
__global__ __launch_bounds__(256) void cvt_kernel(
    const float* __restrict__ x, const float* __restrict__ pw,
    const float* __restrict__ qw)
{
    int blk = blockIdx.x;
    const float* src;
    __half* dst;
    int off;
    if (blk < 1024)      { src = x;  dst = g_xh;  off = blk; }
    else if (blk < 1216) { src = pw; dst = g_wph; off = blk - 1024; }
    else                 { src = qw; dst = g_wh;  off = blk - 1216; }
    int i = (off * 256 + threadIdx.x) * 4;
    float4 v = *(const float4*)(src + i);
    __half2* d2 = (__half2*)(dst + i);
    d2[0] = __floats2half2_rn(v.x, v.y);
    d2[1] = __floats2half2_rn(v.z, v.w);
}

// ============================================================
// smem geometry shared by GEMM kernels
// ============================================================
#define GPH2 72                       // smem pitch in halves (144B)
#define GT2  (128 * GPH2)
#define GEMM_SMEM (4 * GT2 * 2)       // 73728 B

// ============================================================
// Kernel 1: patch-embed GEMM, fp16 mma (unchanged)
// ============================================================
__global__ __launch_bounds__(256, 2) void patch_mma_kernel(
    const float* __restrict__ bias)
{
    extern __shared__ __half hsm[];
    __half* ab[2] = { hsm,           hsm + GT2 };
    __half* bb[2] = { hsm + 2 * GT2, hsm + 3 * GT2 };
    const uint32_t ab_u[2] = { smem_u32(ab[0]), smem_u32(ab[1]) };
    const uint32_t bb_u[2] = { smem_u32(bb[0]), smem_u32(bb[1]) };

    const int tid = threadIdx.x, wid = tid >> 5, lane = tid & 31;
    const int lj = lane & 3, lr = lane >> 2;
    const int wm = wid >> 2, wn = wid & 3;
    const int m0 = blockIdx.y * 128, n0 = blockIdx.x * 128;

    const int aRow = ((lane >> 3) & 1) * 8 + (lane & 7);
    const int aCol = (lane >> 4) * 8;
    const int bRow = (lane >> 4) * 8 + (lane & 7);
    const int bCol = ((lane >> 3) & 1) * 8;

    float4 acc[4][4];
#pragma unroll
    for (int i = 0; i < 4; i++)
#pragma unroll
        for (int j = 0; j < 4; j++) acc[i][j] = make_float4(0.f, 0.f, 0.f, 0.f);

#define PAT_ISSUE(KT, B) do {                                                  \
    _Pragma("unroll")                                                          \
    for (int i2 = 0; i2 < 4; i2++) {                                           \
        int c = tid + i2 * 256;                                                \
        int r = c >> 3, cl = c & 7;                                            \
        int tok = m0 + r;                                                      \
        int k = (KT) + cl * 8;                                                 \
        cp16(ab_u[B] + (r * GPH2 + cl * 8) * 2,                                \
             g_xh + ((tok >> 6) * 16 + (k >> 4)) * 1024                        \
                  + (tok & 63) * 16 + (k & 15));                               \
        cp16(bb_u[B] + (r * GPH2 + cl * 8) * 2,                                \
             g_wph + (n0 + r) * KPATCH + (KT) + cl * 8);                       \
    } } while (0)

    PAT_ISSUE(0, 0);  CP_COMMIT();
    PAT_ISSUE(64, 1); CP_COMMIT();

    const int NIT = KPATCH / 64;   // 4
    for (int it = 0; it < NIT; it++) {
        const int b = it & 1;
        CP_WAIT1();
        __syncthreads();
        const uint32_t Au = ab_u[b];
        const uint32_t Bu = bb_u[b];
#pragma unroll
        for (int gc = 0; gc < 4; gc++) {
            uint32_t af[4][4];
#pragma unroll
            for (int mt = 0; mt < 4; mt++) {
                uint32_t addr = Au + (((wm * 64 + mt * 16 + aRow) * GPH2)
                                      + gc * 16 + aCol) * 2;
                LDSM_X4(af[mt][0], af[mt][1], af[mt][2], af[mt][3], addr);
            }
#pragma unroll
            for (int j = 0; j < 2; j++) {
                uint32_t b0, b1, b2, b3;
                uint32_t addr = Bu + (((wn * 32 + j * 16 + bRow) * GPH2)
                                      + gc * 16 + bCol) * 2;
                LDSM_X4(b0, b1, b2, b3, addr);
#pragma unroll
                for (int mt = 0; mt < 4; mt++) {
                    mma16(acc[mt][2 * j],     af[mt], b0, b1);
                    mma16(acc[mt][2 * j + 1], af[mt], b2, b3);
                }
            }
        }
        __syncthreads();
        if (it + 2 < NIT) PAT_ISSUE((it + 2) * 64, b);
        CP_COMMIT();
    }

#pragma unroll
    for (int nt = 0; nt < 4; nt++) {
        int n = n0 + wn * 32 + nt * 8 + 2 * lj;
        float b0 = bias[n], b1 = bias[n + 1];
#pragma unroll
        for (int mt = 0; mt < 4; mt++) {
            int row = m0 + wm * 64 + mt * 16 + lr;
            *(float2*)&g_tok[row * EMBED + n] =
                make_float2(acc[mt][nt].x + b0, acc[mt][nt].y + b1);
            *(float2*)&g_tok[(row + 8) * EMBED + n] =
                make_float2(acc[mt][nt].z + b0, acc[mt][nt].w + b1);
        }
    }
}

// ============================================================
// Kernel 2: LayerNorm -> fp16 tokens
// ============================================================
__device__ __forceinline__ float block_sum256(float v) {
    __shared__ float sh[8];
    __syncthreads();
    const int lane = threadIdx.x & 31, wrp = threadIdx.x >> 5;
#pragma unroll
    for (int o = 16; o > 0; o >>= 1) v += __shfl_xor_sync(0xffffffffu, v, o);
    if (lane == 0) sh[wrp] = v;
    __syncthreads();
    if (wrp == 0) {
        v = (lane < 8) ? sh[lane] : 0.f;
#pragma unroll
        for (int o = 4; o > 0; o >>= 1) v += __shfl_xor_sync(0xffffffffu, v, o);
        if (lane == 0) sh[0] = v;
    }
    __syncthreads();
    return sh[0];
}

__global__ __launch_bounds__(256) void ln_kernel(
    const float* __restrict__ gamma, const float* __restrict__ beta)
{
    const int n = blockIdx.x;
    const int t = threadIdx.x;
    const float* row = &g_tok[n * EMBED];
    __half* hrow = &g_tok_h[n * EMBED];
    float v0 = row[t], v1 = row[t + 256], v2 = row[t + 512];
    float total = block_sum256(v0 + v1 + v2);
    float mu = total * (1.f / EMBED);
    float d0 = v0 - mu, d1 = v1 - mu, d2 = v2 - mu;
    float tot2 = block_sum256(d0 * d0 + d1 * d1 + d2 * d2);
    float inv = rsqrtf(tot2 * (1.f / EMBED) + 1e-6f);
    hrow[t]       = __float2half(d0 * inv * gamma[t]       + beta[t]);
    hrow[t + 256] = __float2half(d1 * inv * gamma[t + 256] + beta[t + 256]);
    hrow[t + 512] = __float2half(d2 * inv * gamma[t + 512] + beta[t + 512]);
}

// ============================================================
// Kernel 3: QKV GEMM, fp16 mma + ldmatrix, k-tile 64 (unchanged)
// ============================================================
__global__ __launch_bounds__(256, 2) void qkv_kernel()
{
    extern __shared__ __half hsm[];
    __half* ab[2] = { hsm,           hsm + GT2 };
    __half* bb[2] = { hsm + 2 * GT2, hsm + 3 * GT2 };
    const uint32_t ab_u[2] = { smem_u32(ab[0]), smem_u32(ab[1]) };
    const uint32_t bb_u[2] = { smem_u32(bb[0]), smem_u32(bb[1]) };

    const int tid = threadIdx.x, wid = tid >> 5, lane = tid & 31;
    const int lj = lane & 3, lr = lane >> 2;
    const int wm = wid >> 2, wn = wid & 3;
    const int m0 = blockIdx.y * 128, n0 = blockIdx.x * 128;

    const int aRow = ((lane >> 3) & 1) * 8 + (lane & 7);
    const int aCol = (lane >> 4) * 8;
    const int bRow = (lane >> 4) * 8 + (lane & 7);
    const int bCol = ((lane >> 3) & 1) * 8;

    float4 acc[4][4];
#pragma unroll
    for (int i = 0; i < 4; i++)
#pragma unroll
        for (int j = 0; j < 4; j++) acc[i][j] = make_float4(0.f, 0.f, 0.f, 0.f);

#define QKV_ISSUE(KT, B) do {                                                  \
    _Pragma("unroll")                                                          \
    for (int i = 0; i < 4; i++) {                                              \
        int c = tid + i * 256;                                                 \
        int r = c >> 3, cl = c & 7;                                            \
        cp16(ab_u[B] + (r * GPH2 + cl * 8) * 2,                                \
             g_tok_h + (m0 + r) * EMBED + (KT) + cl * 8);                      \
        cp16(bb_u[B] + (r * GPH2 + cl * 8) * 2,                                \
             g_wh + (n0 + r) * EMBED + (KT) + cl * 8);                         \
    } } while (0)

    QKV_ISSUE(0, 0);  CP_COMMIT();
    QKV_ISSUE(64, 1); CP_COMMIT();

    const int NIT = EMBED / 64;   // 12
    for (int it = 0; it < NIT; it++) {
        const int b = it & 1;
        CP_WAIT1();
        __syncthreads();
        const uint32_t Au = ab_u[b];
        const uint32_t Bu = bb_u[b];
#pragma unroll
        for (int gc = 0; gc < 4; gc++) {
            uint32_t af[4][4];
#pragma unroll
            for (int mt = 0; mt < 4; mt++) {
                uint32_t addr = Au + (((wm * 64 + mt * 16 + aRow) * GPH2)
                                      + gc * 16 + aCol) * 2;
                LDSM_X4(af[mt][0], af[mt][1], af[mt][2], af[mt][3], addr);
            }
#pragma unroll
            for (int j = 0; j < 2; j++) {
                uint32_t b0, b1, b2, b3;
                uint32_t addr = Bu + (((wn * 32 + j * 16 + bRow) * GPH2)
                                      + gc * 16 + bCol) * 2;
                LDSM_X4(b0, b1, b2, b3, addr);
#pragma unroll
                for (int mt = 0; mt < 4; mt++) {
                    mma16(acc[mt][2 * j],     af[mt], b0, b1);
                    mma16(acc[mt][2 * j + 1], af[mt], b2, b3);
                }
            }
        }
        __syncthreads();
        if (it + 2 < NIT) QKV_ISSUE((it + 2) * 64, b);
        CP_COMMIT();
    }

#pragma unroll
    for (int nt = 0; nt < 4; nt++) {
        int n = n0 + wn * 32 + nt * 8 + 2 * lj;
        int s = n / EMBED;
        int r = n % EMBED;
        int hh = r / DHEAD, dd = r % DHEAD;
#pragma unroll
        for (int mt = 0; mt < 4; mt++) {
            int row = m0 + wm * 64 + mt * 16 + lr;
            if (s < 2) {
                __half* dst = ((s == 0) ? g_qh : g_kh)
                            + (hh * N_TOK + row) * DHEAD + dd;
                *(__half2*)dst = __floats2half2_rn(acc[mt][nt].x, acc[mt][nt].y);
                *(__half2*)(dst + 8 * DHEAD) =
                    __floats2half2_rn(acc[mt][nt].z, acc[mt][nt].w);
            } else {
                __half* dst = g_vt + (hh * DHEAD + dd) * N_TOK + row;
                dst[0]          = __float2half(acc[mt][nt].x);
                dst[N_TOK]      = __float2half(acc[mt][nt].y);
                dst[8]          = __float2half(acc[mt][nt].z);
                dst[N_TOK + 8]  = __float2half(acc[mt][nt].w);
            }
        }
    }
}

// ============================================================
// Kernel 4: flash attention.
// QK in f16-acc mma (full rate); softmax scale pre-folded into Q
// fragments, so S accumulators ARE the exp2 args: ex2.approx.f16x2
// in place, output feeds PV directly. PV + l stay f32-acc.
// CTA = (head, 128 q), 4 warps x 2 m-tiles, 3 CTAs/SM.
// ============================================================
#define AQ   128
#define AKV  64
#define KPITCH 72
#define ATILEH (AKV * KPITCH)
#define ATH  128

__global__ __launch_bounds__(ATH, 3) void attn_kernel(float* __restrict__ out)
{
    __shared__ __half hsm[4 * ATILEH];           // 36,864 B
    __half* kb[2] = { hsm,              hsm + ATILEH };
    __half* vb[2] = { hsm + 2 * ATILEH, hsm + 3 * ATILEH };
    const uint32_t kb_u[2] = { smem_u32(kb[0]), smem_u32(kb[1]) };
    const uint32_t vb_u[2] = { smem_u32(vb[0]), smem_u32(vb[1]) };

    const int tid = threadIdx.x, wid = tid >> 5, lane = tid & 31;
    const int lj = lane & 3, lr = lane >> 2;
    const int h = blockIdx.y, q0 = blockIdx.x * AQ;

    const int bRow = (lane >> 4) * 8 + (lane & 7);
    const int bCol = ((lane >> 3) & 1) * 8;
    const uint32_t ONEH2 = 0x3C003C00u;
    // 0.125 * log2(e) in packed fp16
    const uint32_t CEXP2 = (uint32_t)__half_as_ushort(__float2half(0.180336880f))
                         * 0x00010001u;

    const __half* Kh  = g_kh + h * N_TOK * DHEAD;
    const __half* Vth = g_vt + h * DHEAD * N_TOK;

    // Q fragments: 2 m-tiles of 16 rows per warp, pre-scaled by CEXP
    uint32_t qa[2][4][4];
#pragma unroll
    for (int mt = 0; mt < 2; mt++) {
        const __half* Q0 = g_qh
            + (h * N_TOK + q0 + wid * 32 + mt * 16 + lr) * DHEAD;
#pragma unroll
        for (int gc = 0; gc < 4; gc++) {
            int base = gc * 16 + 2 * lj;
            qa[mt][gc][0] = h2mul(ldh2(Q0 + base),                 CEXP2);
            qa[mt][gc][1] = h2mul(ldh2(Q0 + 8 * DHEAD + base),     CEXP2);
            qa[mt][gc][2] = h2mul(ldh2(Q0 + base + 8),             CEXP2);
            qa[mt][gc][3] = h2mul(ldh2(Q0 + 8 * DHEAD + base + 8), CEXP2);
        }
    }

    float4 oacc[2][8];
#pragma unroll
    for (int mt = 0; mt < 2; mt++)
#pragma unroll
        for (int i = 0; i < 8; i++) oacc[mt][i] = make_float4(0.f, 0.f, 0.f, 0.f);
    float4 lacc[2];
    lacc[0] = make_float4(0.f, 0.f, 0.f, 0.f);
    lacc[1] = make_float4(0.f, 0.f, 0.f, 0.f);

#define ATT_ISSUE(T, B) do {                                                   \
    _Pragma("unroll")                                                          \
    for (int i = 0; i < 4; i++) {                                              \
        int c = tid + i * ATH;                                                 \
        int r = c >> 3, cl = c & 7;                                            \
        cp16(kb_u[B] + (r * KPITCH + cl * 8) * 2,                              \
             Kh + ((T) * AKV + r) * DHEAD + cl * 8);                           \
        cp16(vb_u[B] + (r * KPITCH + cl * 8) * 2,                              \
             Vth + r * N_TOK + (T) * AKV + cl * 8);                            \
    } } while (0)

    ATT_ISSUE(0, 0); CP_COMMIT();
    ATT_ISSUE(1, 1); CP_COMMIT();

    const int NT = N_TOK / AKV;   // 64
    for (int t = 0; t < NT; t++) {
        const int b = t & 1;
        CP_WAIT1();
        __syncthreads();
        const uint32_t Ku = kb_u[b];
        const uint32_t Vu = vb_u[b];

#pragma unroll
        for (int pair = 0; pair < 4; pair++) {    // 16-kv chunk
            // S accumulators in f16x2 (exp2-args, thanks to pre-scaled Q)
            uint32_t pa[2][4];
#pragma unroll
            for (int mt = 0; mt < 2; mt++)
#pragma unroll
                for (int i = 0; i < 4; i++) pa[mt][i] = 0u;
#pragma unroll
            for (int gc = 0; gc < 4; gc++) {
                uint32_t k0, k1, k2, k3;
                uint32_t addr = Ku + (((pair * 16 + bRow) * KPITCH)
                                      + gc * 16 + bCol) * 2;
                LDSM_X4(k0, k1, k2, k3, addr);
#pragma unroll
                for (int mt = 0; mt < 2; mt++) {
                    mma16h(pa[mt][0], pa[mt][1], qa[mt][gc], k0, k1);
                    mma16h(pa[mt][2], pa[mt][3], qa[mt][gc], k2, k3);
                }
            }
            // exp2 in place: pa becomes P (fp16), ready as PV A-frags
#pragma unroll
            for (int mt = 0; mt < 2; mt++) {
                h2exp2(pa[mt][0]); h2exp2(pa[mt][1]);
                h2exp2(pa[mt][2]); h2exp2(pa[mt][3]);
            }
#pragma unroll
            for (int dtj = 0; dtj < 4; dtj++) {
                uint32_t v0, v1, v2, v3;
                uint32_t addr = Vu + (((dtj * 16 + bRow) * KPITCH)
                                      + pair * 16 + bCol) * 2;
                LDSM_X4(v0, v1, v2, v3, addr);
#pragma unroll
                for (int mt = 0; mt < 2; mt++) {
                    mma16(oacc[mt][2 * dtj],     pa[mt], v0, v1);
                    mma16(oacc[mt][2 * dtj + 1], pa[mt], v2, v3);
                }
            }
            mma16(lacc[0], pa[0], ONEH2, ONEH2);   // l = row-sum of P
            mma16(lacc[1], pa[1], ONEH2, ONEH2);
        }

        __syncthreads();
        if (t + 2 < NT) ATT_ISSUE(t + 2, b);
        CP_COMMIT();
    }

    // ---- epilogue: l straight from lacc (no shuffles) ----
#pragma unroll
    for (int mt = 0; mt < 2; mt++) {
        const float inv_lo = 1.f / lacc[mt].x;
        const float inv_hi = 1.f / lacc[mt].z;
        const int row = q0 + wid * 32 + mt * 16 + lr;
        float* o0 = out + row * EMBED + h * DHEAD + 2 * lj;
        float* o8 = o0 + 8 * EMBED;
#pragma unroll
        for (int dt = 0; dt < 8; dt++) {
            *(float2*)(o0 + dt * 8) = make_float2(oacc[mt][dt].x * inv_lo,
                                                  oacc[mt][dt].y * inv_lo);
            *(float2*)(o8 + dt * 8) = make_float2(oacc[mt][dt].z * inv_hi,
                                                  oacc[mt][dt].w * inv_hi);
        }
    }
}

// ============================================================
extern "C" void kernel_launch(void* const* d_in, const int* in_sizes, int n_in,
                              void* d_out, int out_size)
{
    const float* x  = (const float*)d_in[0];
    const float* pw = (const float*)d_in[1];
    const float* pb = (const float*)d_in[2];
    const float* lg = (const float*)d_in[3];
    const float* lb = (const float*)d_in[4];
    const float* qw = (const float*)d_in[5];
    float* out = (float*)d_out;

    cudaFuncSetAttribute(qkv_kernel,
                         cudaFuncAttributeMaxDynamicSharedMemorySize, GEMM_SMEM);
    cudaFuncSetAttribute(patch_mma_kernel,
                         cudaFuncAttributeMaxDynamicSharedMemorySize, GEMM_SMEM);

    cvt_kernel<<<2944, 256>>>(x, pw, qw);
    patch_mma_kernel<<<dim3(EMBED / 128, N_TOK / 128), 256, GEMM_SMEM>>>(pb);
    ln_kernel<<<N_TOK, 256>>>(lg, lb);
    qkv_kernel<<<dim3(2304 / 128, N_TOK / 128), 256, GEMM_SMEM>>>();
    attn_kernel<<<dim3(N_TOK / AQ, NHEAD), ATH>>>(out);
}